// round 10
// baseline (speedup 1.0000x reference)
#include <cuda_runtime.h>
#include <math.h>

#define TT 150
#define NB 8
#define VV 2048
#define CC 16
#define LL 64
#define L3 192
#define EE 32768
#define NV (NB*VV)   // 16384

// ---------------- static device scratch (total ~2.52 GB of .bss — under aarch64 adrp reach) ----
__device__ float g_xe [(size_t)TT*NV*LL];   // encoder output; later overwritten with z
__device__ float g_gi [(size_t)TT*NV*L3];   // gi buffer, reused: pass1=domain, pass2=correction
__device__ float g_hd [NV*LL];              // domain hidden
__device__ float g_h  [NV*LL];              // correction hidden
__device__ float g_cz [NV*LL];              // z_D @ ode_W1[64:128] + ode_b1
__device__ float g_Wcd[LL*L3];              // W_gd @ gd_Wi
__device__ float g_Wcc[LL*L3];              // W_gc @ gc_Wi
__device__ int   g_deg[VV];
__device__ int   g_cur[VV];
__device__ int   g_rowptr[VV+1];
__device__ int   g_eid [EE];
__device__ int   g_cols[EE];
__device__ float g_vals[EE];

__device__ __forceinline__ float sigmf_(float x){ return 1.f/(1.f+expf(-x)); }

// ---------------- CSR build (deterministic: rows sorted by edge id) ----------------
__global__ void k_csr0(){
    int v = blockIdx.x*blockDim.x + threadIdx.x;
    if (v < VV) g_deg[v] = 0;
}
__global__ void k_count(const int* __restrict__ ei){
    int e = blockIdx.x*blockDim.x + threadIdx.x;
    if (e < EE) atomicAdd(&g_deg[ei[EE+e]], 1);
}
__global__ void k_prefix(){
    int acc = 0;
    g_rowptr[0] = 0;
    for (int v = 0; v < VV; v++){ acc += g_deg[v]; g_rowptr[v+1] = acc; g_cur[v] = g_rowptr[v]; }
}
__global__ void k_fill(const int* __restrict__ ei){
    int e = blockIdx.x*blockDim.x + threadIdx.x;
    if (e < EE){
        int pos = atomicAdd(&g_cur[ei[EE+e]], 1);
        g_eid[pos] = e;
    }
}
__global__ void k_sort(const int* __restrict__ ei, const float* __restrict__ attr){
    int v = blockIdx.x*blockDim.x + threadIdx.x;
    if (v >= VV) return;
    int s = g_rowptr[v], e = g_rowptr[v+1];
    for (int i = s+1; i < e; i++){
        int key = g_eid[i]; int k = i-1;
        while (k >= s && g_eid[k] > key){ g_eid[k+1] = g_eid[k]; k--; }
        g_eid[k+1] = key;
    }
    for (int i = s; i < e; i++){
        int id = g_eid[i];
        g_cols[i] = ei[id];       // src
        g_vals[i] = attr[id];
    }
}

// ---------------- weight folding: Wc = W_g @ Wi  ([64,64]@[64,192]) ----------------
__global__ void k_fold(const float* __restrict__ Wgd, const float* __restrict__ Wid,
                       const float* __restrict__ Wgc, const float* __restrict__ Wic){
    int i = blockIdx.x;          // row 0..63
    int j = threadIdx.x;         // col 0..191
    const float* Wg = (blockIdx.y == 0) ? Wgd : Wgc;
    const float* Wi = (blockIdx.y == 0) ? Wid : Wic;
    float*       Wc = (blockIdx.y == 0) ? g_Wcd : g_Wcc;
    float acc = 0.f;
    #pragma unroll
    for (int k = 0; k < LL; k++) acc += Wg[i*LL + k] * Wi[k*L3 + j];
    Wc[i*L3 + j] = acc;
}

__global__ void k_zero_hd(){
    int i = blockIdx.x*blockDim.x + threadIdx.x;
    if (i < NV*LL) g_hd[i] = 0.f;
}
__global__ void k_copyh(){
    int i = blockIdx.x*blockDim.x + threadIdx.x;
    if (i < NV*LL) g_h[i] = g_xe[i];      // h0 = xe[0]
}

// ---------------- encoder: xe[t,nv,l] = sum_c x[nv,c,t]*W_enc[c,l] + b ----------------
__global__ void k_encode(const float* __restrict__ x, const float* __restrict__ W,
                         const float* __restrict__ b){
    __shared__ float xs[CC*32];
    __shared__ float Ws[CC*LL];
    __shared__ float bs[LL];
    int blk = blockIdx.x;
    int nv = blk / 5;
    int t0 = (blk % 5) * 32;
    int tid = threadIdx.x;
    for (int i = tid; i < CC*32; i += 256){
        int c = i / 32, tl = i % 32, t = t0 + tl;
        xs[c*32 + tl] = (t < TT) ? x[((size_t)nv*CC + c)*TT + t] : 0.f;
    }
    for (int i = tid; i < CC*LL; i += 256) Ws[i] = W[i];
    if (tid < LL) bs[tid] = b[tid];
    __syncthreads();
    int l = tid & 63, tg = tid >> 6;
    for (int tl = tg; tl < 32; tl += 4){
        int t = t0 + tl;
        if (t >= TT) break;
        float acc = bs[l];
        #pragma unroll
        for (int c = 0; c < CC; c++) acc += xs[c*32 + tl] * Ws[c*LL + l];
        g_xe[((size_t)t*NV + nv)*LL + l] = acc;
    }
}

// ---------------- fused gather + GEMM: gi = (S.xe)@Wc + b for all t (one pass) ----------
// grid: TT*NB*16 = 19200 blocks, 384 threads, dyn smem 82688
__global__ void __launch_bounds__(384) k_gather(int pass, const float* __restrict__ bias){
    extern __shared__ float sm[];
    float* Ws  = sm;                 // [64][192]
    float* agg = sm + 64*L3;         // [128][64]
    float* bs  = agg + 128*LL;       // [192]
    const float* Wc = pass ? g_Wcc : g_Wcd;
    int b = blockIdx.x;
    int t   = b >> 7;
    int rem = b & 127;
    int n   = rem >> 4;
    int v0  = (rem & 15) * 128;
    int tid = threadIdx.x;

    for (int i = tid; i < 64*L3; i += 384) Ws[i] = Wc[i];
    if (tid < L3) bs[tid] = bias[tid];

    // gather phase (warp-uniform row per warp-half)
    const float* xb = g_xe + ((size_t)t*NV + (size_t)n*VV) * LL;
    int lane = tid & 63, rg = tid >> 6;   // rg 0..5
    for (int r = rg; r < 128; r += 6){
        int v = v0 + r;
        int s = g_rowptr[v], e = g_rowptr[v+1];
        float acc = 0.f;
        for (int idx = s; idx < e; idx++)
            acc += xb[(size_t)g_cols[idx]*LL + lane] * g_vals[idx];
        agg[r*LL + lane] = acc;
    }
    __syncthreads();

    // GEMM: agg[128x64] @ Ws[64x192], 8x8 register tiles
    int ct = tid % 24, rt = tid / 24;     // rt 0..15
    int r0 = rt * 8, c0 = ct * 8;
    float acc[8][8];
    #pragma unroll
    for (int i = 0; i < 8; i++)
        #pragma unroll
        for (int j = 0; j < 8; j++) acc[i][j] = bs[c0 + j];

    #pragma unroll 4
    for (int k0 = 0; k0 < 64; k0 += 4){
        float4 a[8];
        #pragma unroll
        for (int i = 0; i < 8; i++) a[i] = *(const float4*)(agg + (r0+i)*LL + k0);
        #pragma unroll
        for (int kk = 0; kk < 4; kk++){
            float4 w0 = *(const float4*)(Ws + (k0+kk)*L3 + c0);
            float4 w1 = *(const float4*)(Ws + (k0+kk)*L3 + c0 + 4);
            #pragma unroll
            for (int i = 0; i < 8; i++){
                float av = (kk==0) ? a[i].x : (kk==1) ? a[i].y : (kk==2) ? a[i].z : a[i].w;
                acc[i][0] += av*w0.x; acc[i][1] += av*w0.y;
                acc[i][2] += av*w0.z; acc[i][3] += av*w0.w;
                acc[i][4] += av*w1.x; acc[i][5] += av*w1.y;
                acc[i][6] += av*w1.z; acc[i][7] += av*w1.w;
            }
        }
    }
    float* outp = g_gi + ((size_t)t*NV + (size_t)n*VV + v0) * L3;
    #pragma unroll
    for (int i = 0; i < 8; i++){
        *(float4*)(outp + (size_t)(r0+i)*L3 + c0)     = make_float4(acc[i][0],acc[i][1],acc[i][2],acc[i][3]);
        *(float4*)(outp + (size_t)(r0+i)*L3 + c0 + 4) = make_float4(acc[i][4],acc[i][5],acc[i][6],acc[i][7]);
    }
}

// ---------------- domain GRU step: hd = GRU(gi[t], hd) ----------------
// grid 512 (32 rows/block), 192 threads, dyn smem 90112
__global__ void __launch_bounds__(192) k_domstep(int t, const float* __restrict__ Wh){
    extern __shared__ float sm[];
    float* Whs  = sm;               // [64][192]
    float* hs   = Whs + 64*L3;      // [32][64]
    float* comb = hs + 32*LL;       // [32][192]
    float* hns  = comb + 32*L3;     // [32][64]
    int tid = threadIdx.x;
    int row0 = blockIdx.x * 32;
    for (int i = tid; i < (64*L3)/4; i += 192) ((float4*)Whs)[i] = ((const float4*)Wh)[i];
    for (int i = tid; i < (32*LL)/4; i += 192) ((float4*)hs)[i] = ((const float4*)(g_hd + (size_t)row0*LL))[i];
    __syncthreads();

    // gh = hs[32x64] @ Whs[64x192], 4x8 tiles
    int ct = tid % 24, rt = tid / 24;   // rt 0..7
    int r0 = rt * 4, c0 = ct * 8;
    float acc[4][8];
    #pragma unroll
    for (int i = 0; i < 4; i++)
        #pragma unroll
        for (int j = 0; j < 8; j++) acc[i][j] = 0.f;

    #pragma unroll 4
    for (int k0 = 0; k0 < 64; k0 += 4){
        float4 a[4];
        #pragma unroll
        for (int i = 0; i < 4; i++) a[i] = *(const float4*)(hs + (r0+i)*LL + k0);
        #pragma unroll
        for (int kk = 0; kk < 4; kk++){
            float4 w0 = *(const float4*)(Whs + (k0+kk)*L3 + c0);
            float4 w1 = *(const float4*)(Whs + (k0+kk)*L3 + c0 + 4);
            #pragma unroll
            for (int i = 0; i < 4; i++){
                float av = (kk==0) ? a[i].x : (kk==1) ? a[i].y : (kk==2) ? a[i].z : a[i].w;
                acc[i][0] += av*w0.x; acc[i][1] += av*w0.y;
                acc[i][2] += av*w0.z; acc[i][3] += av*w0.w;
                acc[i][4] += av*w1.x; acc[i][5] += av*w1.y;
                acc[i][6] += av*w1.z; acc[i][7] += av*w1.w;
            }
        }
    }
    const float* gi = g_gi + ((size_t)t*NV + row0) * L3;
    #pragma unroll
    for (int i = 0; i < 4; i++){
        int r = r0 + i;
        float4 gA = *(const float4*)(gi + (size_t)r*L3 + c0);
        float4 gB = *(const float4*)(gi + (size_t)r*L3 + c0 + 4);
        *(float4*)(comb + r*L3 + c0)     = make_float4(acc[i][0]+gA.x, acc[i][1]+gA.y, acc[i][2]+gA.z, acc[i][3]+gA.w);
        *(float4*)(comb + r*L3 + c0 + 4) = make_float4(acc[i][4]+gB.x, acc[i][5]+gB.y, acc[i][6]+gB.z, acc[i][7]+gB.w);
        if (c0 >= 128){
            int cc = c0 - 128;
            *(float4*)(hns + r*LL + cc)     = make_float4(acc[i][0],acc[i][1],acc[i][2],acc[i][3]);
            *(float4*)(hns + r*LL + cc + 4) = make_float4(acc[i][4],acc[i][5],acc[i][6],acc[i][7]);
        }
    }
    __syncthreads();
    int jj = tid % 64, rgp = tid / 64;
    for (int r = rgp; r < 32; r += 3){
        float z  = sigmf_(comb[r*L3 + jj]);
        float rr = sigmf_(comb[r*L3 + 64 + jj]);
        float hn = hns[r*LL + jj];
        float nn = tanhf(comb[r*L3 + 128 + jj] + (rr - 1.f)*hn);
        float hp = hs[r*LL + jj];
        g_hd[(size_t)(row0+r)*LL + jj] = (1.f - z)*nn + z*hp;
    }
}

// ---------------- domain MLP + cz precompute ----------------
__global__ void k_dommlp(const float* __restrict__ Wd1, const float* __restrict__ bd1,
                         const float* __restrict__ Wd2, const float* __restrict__ bd2,
                         const float* __restrict__ odeW1, const float* __restrict__ odeb1){
    extern __shared__ float sm[];
    float* W1s = sm;            // W_dom1
    float* W2s = W1s + 4096;    // W_dom2
    float* Wzs = W2s + 4096;    // ode_W1 rows 64..127
    float* hds = Wzs + 4096;    // [16][64]
    float* t1s = hds + 1024;
    float* zDs = t1s + 1024;
    float* b1s = zDs + 1024;
    float* b2s = b1s + 64;
    float* bos = b2s + 64;
    int tid = threadIdx.x;
    int row0 = blockIdx.x * 16;
    for (int i = tid; i < 4096; i += 256){ W1s[i] = Wd1[i]; W2s[i] = Wd2[i]; Wzs[i] = odeW1[4096 + i]; }
    for (int i = tid; i < 16*LL; i += 256) hds[i] = g_hd[(size_t)row0*LL + i];
    if (tid < 64){ b1s[tid] = bd1[tid]; b2s[tid] = bd2[tid]; bos[tid] = odeb1[tid]; }
    __syncthreads();
    int j = tid & 63, rg = tid >> 6;
    for (int r = rg; r < 16; r += 4){
        float acc = b1s[j];
        #pragma unroll
        for (int k = 0; k < LL; k++) acc += hds[r*LL + k] * W1s[k*LL + j];
        t1s[r*LL + j] = tanhf(acc);
    }
    __syncthreads();
    for (int r = rg; r < 16; r += 4){
        float acc = b2s[j];
        #pragma unroll
        for (int k = 0; k < LL; k++) acc += t1s[r*LL + k] * W2s[k*LL + j];
        zDs[r*LL + j] = acc;
    }
    __syncthreads();
    for (int r = rg; r < 16; r += 4){
        float acc = bos[j];
        #pragma unroll
        for (int k = 0; k < LL; k++) acc += zDs[r*LL + k] * Wzs[k*LL + j];
        g_cz[(size_t)(row0+r)*LL + j] = acc;
    }
}

// ---------------- correction step: ODE + GRU; writes h and z[t] ----------------
// grid 256 (64 rows/block), 192 threads, dyn smem 196864
__global__ void __launch_bounds__(192) k_corrstep(int t, const float* __restrict__ odeW1,
                           const float* __restrict__ odeW2, const float* __restrict__ odeb2,
                           const float* __restrict__ Wh){
    extern __shared__ float sm[];
    float* Whs  = sm;               // [64][192]
    float* W1s  = Whs + 64*L3;      // ode_W1 rows 0..63
    float* W2s  = W1s + 4096;       // ode_W2
    float* hs   = W2s + 4096;       // [64][64]
    float* czs  = hs  + 64*LL;      // [64][64]  (aliased as hns later)
    float* t1s  = czs + 64*LL;      // [64][64]
    float* hos  = t1s + 64*LL;      // [64][64]  h_ode
    float* comb = hos + 64*LL;      // [64][192]
    float* b2s  = comb + 64*L3;     // 64
    float* hns  = czs;              // alias: czs dead after t1s
    int tid = threadIdx.x;
    int row0 = blockIdx.x * 64;
    for (int i = tid; i < (64*L3)/4; i += 192) ((float4*)Whs)[i] = ((const float4*)Wh)[i];
    for (int i = tid; i < 1024; i += 192){ ((float4*)W1s)[i] = ((const float4*)odeW1)[i];
                                           ((float4*)W2s)[i] = ((const float4*)odeW2)[i]; }
    for (int i = tid; i < (64*LL)/4; i += 192){
        ((float4*)hs )[i] = ((const float4*)(g_h  + (size_t)row0*LL))[i];
        ((float4*)czs)[i] = ((const float4*)(g_cz + (size_t)row0*LL))[i];
    }
    if (tid < 64) b2s[tid] = odeb2[tid];
    __syncthreads();

    // ODE GEMM1: t1 = tanh(hs @ W1s + cz)   (128 active threads, 4x8 tiles over 64x64)
    if (tid < 128){
        int rt = tid >> 3, ct = tid & 7;    // 16 x 8
        int r0 = rt * 4, c0 = ct * 8;
        float acc[4][8];
        #pragma unroll
        for (int i = 0; i < 4; i++){
            float4 cA = *(const float4*)(czs + (r0+i)*LL + c0);
            float4 cB = *(const float4*)(czs + (r0+i)*LL + c0 + 4);
            acc[i][0]=cA.x; acc[i][1]=cA.y; acc[i][2]=cA.z; acc[i][3]=cA.w;
            acc[i][4]=cB.x; acc[i][5]=cB.y; acc[i][6]=cB.z; acc[i][7]=cB.w;
        }
        #pragma unroll 4
        for (int k0 = 0; k0 < 64; k0 += 4){
            float4 a[4];
            #pragma unroll
            for (int i = 0; i < 4; i++) a[i] = *(const float4*)(hs + (r0+i)*LL + k0);
            #pragma unroll
            for (int kk = 0; kk < 4; kk++){
                float4 w0 = *(const float4*)(W1s + (k0+kk)*LL + c0);
                float4 w1 = *(const float4*)(W1s + (k0+kk)*LL + c0 + 4);
                #pragma unroll
                for (int i = 0; i < 4; i++){
                    float av = (kk==0)?a[i].x:(kk==1)?a[i].y:(kk==2)?a[i].z:a[i].w;
                    acc[i][0]+=av*w0.x; acc[i][1]+=av*w0.y; acc[i][2]+=av*w0.z; acc[i][3]+=av*w0.w;
                    acc[i][4]+=av*w1.x; acc[i][5]+=av*w1.y; acc[i][6]+=av*w1.z; acc[i][7]+=av*w1.w;
                }
            }
        }
        #pragma unroll
        for (int i = 0; i < 4; i++)
            #pragma unroll
            for (int j = 0; j < 8; j++) t1s[(r0+i)*LL + c0 + j] = tanhf(acc[i][j]);
    }
    __syncthreads();
    // ODE GEMM2: hos = hs + (t1 @ W2s + b2)
    if (tid < 128){
        int rt = tid >> 3, ct = tid & 7;
        int r0 = rt * 4, c0 = ct * 8;
        float acc[4][8];
        #pragma unroll
        for (int i = 0; i < 4; i++)
            #pragma unroll
            for (int j = 0; j < 8; j++) acc[i][j] = b2s[c0 + j];
        #pragma unroll 4
        for (int k0 = 0; k0 < 64; k0 += 4){
            float4 a[4];
            #pragma unroll
            for (int i = 0; i < 4; i++) a[i] = *(const float4*)(t1s + (r0+i)*LL + k0);
            #pragma unroll
            for (int kk = 0; kk < 4; kk++){
                float4 w0 = *(const float4*)(W2s + (k0+kk)*LL + c0);
                float4 w1 = *(const float4*)(W2s + (k0+kk)*LL + c0 + 4);
                #pragma unroll
                for (int i = 0; i < 4; i++){
                    float av = (kk==0)?a[i].x:(kk==1)?a[i].y:(kk==2)?a[i].z:a[i].w;
                    acc[i][0]+=av*w0.x; acc[i][1]+=av*w0.y; acc[i][2]+=av*w0.z; acc[i][3]+=av*w0.w;
                    acc[i][4]+=av*w1.x; acc[i][5]+=av*w1.y; acc[i][6]+=av*w1.z; acc[i][7]+=av*w1.w;
                }
            }
        }
        #pragma unroll
        for (int i = 0; i < 4; i++)
            #pragma unroll
            for (int j = 0; j < 8; j++)
                hos[(r0+i)*LL + c0 + j] = hs[(r0+i)*LL + c0 + j] + acc[i][j];
    }
    __syncthreads();

    // GRU GEMM: gh = hos[64x64] @ Whs[64x192], 8x8 tiles (192 threads)
    {
        int ct = tid % 24, rt = tid / 24;   // rt 0..7
        int r0 = rt * 8, c0 = ct * 8;
        float acc[8][8];
        #pragma unroll
        for (int i = 0; i < 8; i++)
            #pragma unroll
            for (int j = 0; j < 8; j++) acc[i][j] = 0.f;
        #pragma unroll 4
        for (int k0 = 0; k0 < 64; k0 += 4){
            float4 a[8];
            #pragma unroll
            for (int i = 0; i < 8; i++) a[i] = *(const float4*)(hos + (r0+i)*LL + k0);
            #pragma unroll
            for (int kk = 0; kk < 4; kk++){
                float4 w0 = *(const float4*)(Whs + (k0+kk)*L3 + c0);
                float4 w1 = *(const float4*)(Whs + (k0+kk)*L3 + c0 + 4);
                #pragma unroll
                for (int i = 0; i < 8; i++){
                    float av = (kk==0)?a[i].x:(kk==1)?a[i].y:(kk==2)?a[i].z:a[i].w;
                    acc[i][0]+=av*w0.x; acc[i][1]+=av*w0.y; acc[i][2]+=av*w0.z; acc[i][3]+=av*w0.w;
                    acc[i][4]+=av*w1.x; acc[i][5]+=av*w1.y; acc[i][6]+=av*w1.z; acc[i][7]+=av*w1.w;
                }
            }
        }
        const float* gi = g_gi + ((size_t)t*NV + row0) * L3;
        #pragma unroll
        for (int i = 0; i < 8; i++){
            int r = r0 + i;
            float4 gA = *(const float4*)(gi + (size_t)r*L3 + c0);
            float4 gB = *(const float4*)(gi + (size_t)r*L3 + c0 + 4);
            *(float4*)(comb + r*L3 + c0)     = make_float4(acc[i][0]+gA.x, acc[i][1]+gA.y, acc[i][2]+gA.z, acc[i][3]+gA.w);
            *(float4*)(comb + r*L3 + c0 + 4) = make_float4(acc[i][4]+gB.x, acc[i][5]+gB.y, acc[i][6]+gB.z, acc[i][7]+gB.w);
            if (c0 >= 128){
                int cc = c0 - 128;
                *(float4*)(hns + r*LL + cc)     = make_float4(acc[i][0],acc[i][1],acc[i][2],acc[i][3]);
                *(float4*)(hns + r*LL + cc + 4) = make_float4(acc[i][4],acc[i][5],acc[i][6],acc[i][7]);
            }
        }
    }
    __syncthreads();
    int jj = tid % 64, rgp = tid / 64;
    for (int r = rgp; r < 64; r += 3){
        float z  = sigmf_(comb[r*L3 + jj]);
        float rr = sigmf_(comb[r*L3 + 64 + jj]);
        float hn = hns[r*LL + jj];
        float nn = tanhf(comb[r*L3 + 128 + jj] + (rr - 1.f)*hn);
        float ho = hos[r*LL + jj];
        float hnew = (1.f - z)*nn + z*ho;
        g_h[(size_t)(row0+r)*LL + jj] = hnew;
        g_xe[((size_t)t*NV + row0 + r)*LL + jj] = hnew;   // z[t]
    }
}

// ---------------- decoder: out[nv,c,t] = z[t,nv,:]@W_dec + b_dec ----------------
__global__ void k_decode(float* __restrict__ out, const float* __restrict__ W,
                         const float* __restrict__ b){
    __shared__ float zs[32*65];
    __shared__ float Ws[LL*CC];
    __shared__ float bs[CC];
    int blk = blockIdx.x;
    int nv = blk / 5;
    int t0 = (blk % 5) * 32;
    int tid = threadIdx.x;
    for (int i = tid; i < 32*LL; i += 256){
        int tl = i >> 6, l = i & 63, t = t0 + tl;
        zs[tl*65 + l] = (t < TT) ? g_xe[((size_t)t*NV + nv)*LL + l] : 0.f;
    }
    for (int i = tid; i < LL*CC; i += 256) Ws[i] = W[i];
    if (tid < CC) bs[tid] = b[tid];
    __syncthreads();
    for (int o = tid; o < 512; o += 256){
        int c = o >> 5, tl = o & 31, t = t0 + tl;
        if (t >= TT) continue;
        float acc = bs[c];
        #pragma unroll
        for (int l = 0; l < LL; l++) acc += zs[tl*65 + l] * Ws[l*CC + c];
        out[((size_t)nv*CC + c)*TT + t] = acc;
    }
}

// ---------------- launch ----------------
extern "C" void kernel_launch(void* const* d_in, const int* in_sizes, int n_in,
                              void* d_out, int out_size){
    const float* x      = (const float*)d_in[0];
    const int*   ei     = (const int*)  d_in[1];
    const float* attr   = (const float*)d_in[2];
    const float* W_enc  = (const float*)d_in[3];
    const float* b_enc  = (const float*)d_in[4];
    const float* W_gd   = (const float*)d_in[5];
    const float* gd_Wi  = (const float*)d_in[6];
    const float* gd_Wh  = (const float*)d_in[7];
    const float* gd_b   = (const float*)d_in[8];
    const float* W_dom1 = (const float*)d_in[9];
    const float* b_dom1 = (const float*)d_in[10];
    const float* W_dom2 = (const float*)d_in[11];
    const float* b_dom2 = (const float*)d_in[12];
    const float* ode_W1 = (const float*)d_in[13];
    const float* ode_b1 = (const float*)d_in[14];
    const float* ode_W2 = (const float*)d_in[15];
    const float* ode_b2 = (const float*)d_in[16];
    const float* W_gc   = (const float*)d_in[17];
    const float* gc_Wi  = (const float*)d_in[18];
    const float* gc_Wh  = (const float*)d_in[19];
    const float* gc_b   = (const float*)d_in[20];
    const float* W_dec  = (const float*)d_in[21];
    const float* b_dec  = (const float*)d_in[22];
    float* out = (float*)d_out;

    const int SM_GATHER = (64*L3 + 128*LL + L3) * 4;                         // 82688
    const int SM_DOM    = (64*L3 + 32*LL + 32*L3 + 32*LL) * 4;               // 90112
    const int SM_CORR   = (64*L3 + 4096 + 4096 + 4*64*LL + 64*L3 + 64) * 4;  // 196864
    const int SM_MLP    = (3*4096 + 3*1024 + 3*64) * 4;                      // 62208

    cudaFuncSetAttribute(k_gather,   cudaFuncAttributeMaxDynamicSharedMemorySize, SM_GATHER);
    cudaFuncSetAttribute(k_domstep,  cudaFuncAttributeMaxDynamicSharedMemorySize, SM_DOM);
    cudaFuncSetAttribute(k_corrstep, cudaFuncAttributeMaxDynamicSharedMemorySize, SM_CORR);
    cudaFuncSetAttribute(k_dommlp,   cudaFuncAttributeMaxDynamicSharedMemorySize, SM_MLP);

    // CSR build (deterministic)
    k_csr0  <<<(VV+255)/256, 256>>>();
    k_count <<<(EE+255)/256, 256>>>(ei);
    k_prefix<<<1, 1>>>();
    k_fill  <<<(EE+255)/256, 256>>>(ei);
    k_sort  <<<(VV+255)/256, 256>>>(ei, attr);

    // weight folding + init
    k_fold   <<<dim3(64, 2), L3>>>(W_gd, gd_Wi, W_gc, gc_Wi);
    k_zero_hd<<<(NV*LL+255)/256, 256>>>();

    // encoder
    k_encode<<<NV*5, 256>>>(x, W_enc, b_enc);

    // pass 1: gi for domain GRU; then domain scan + MLP
    k_gather<<<TT*NB*16, 384, SM_GATHER>>>(0, gd_b);
    for (int t = 0; t < TT; t++)
        k_domstep<<<NV/32, 192, SM_DOM>>>(t, gd_Wh);
    k_dommlp<<<NV/16, 256, SM_MLP>>>(W_dom1, b_dom1, W_dom2, b_dom2, ode_W1, ode_b1);

    // pass 2: gi for correction GRU (reuses g_gi); then correction scan
    k_gather<<<TT*NB*16, 384, SM_GATHER>>>(1, gc_b);
    k_copyh<<<(NV*LL+255)/256, 256>>>();
    for (int t = 1; t < TT; t++)
        k_corrstep<<<NV/64, 192, SM_CORR>>>(t, ode_W1, ode_W2, ode_b2, gc_Wh);

    // decoder
    k_decode<<<NV*5, 256>>>(out, W_dec, b_dec);
}

// round 11
// speedup vs baseline: 1.2619x; 1.2619x over previous
#include <cuda_runtime.h>
#include <math.h>

#define TT 150
#define NB 8
#define VV 2048
#define CC 16
#define LL 64
#define L3 192
#define EE 32768
#define NV (NB*VV)   // 16384

// ---------------- static device scratch (~2.52 GB .bss — under aarch64 adrp reach) ----
__device__ float g_xe [(size_t)TT*NV*LL];   // encoder output; later overwritten with z
__device__ float g_gi [(size_t)TT*NV*L3];   // gi buffer, reused: pass1=domain, pass2=correction
__device__ float g_hd [NV*LL];              // domain hidden (final)
__device__ float g_cz [NV*LL];              // z_D @ ode_W1[64:128] + ode_b1
__device__ float g_Wcd[LL*L3];              // W_gd @ gd_Wi
__device__ float g_Wcc[LL*L3];              // W_gc @ gc_Wi
__device__ int   g_rowptr[VV+1];
__device__ int   g_eid [EE];
__device__ int   g_cols[EE];
__device__ float g_vals[EE];

__device__ __forceinline__ float sigmf_(float x){ return 1.f/(1.f+expf(-x)); }

// ---------------- CSR build: ONE block, deterministic (rows sorted by edge id) --------
__global__ void __launch_bounds__(1024) k_csr(const int* __restrict__ ei,
                                              const float* __restrict__ attr){
    __shared__ int sdeg[VV];
    __shared__ int scur[VV];
    int tid = threadIdx.x;
    for (int v = tid; v < VV; v += 1024) sdeg[v] = 0;
    __syncthreads();
    for (int e = tid; e < EE; e += 1024) atomicAdd(&sdeg[ei[EE+e]], 1);
    __syncthreads();
    if (tid == 0){
        int acc = 0;
        g_rowptr[0] = 0;
        for (int v = 0; v < VV; v++){ scur[v] = acc; acc += sdeg[v]; g_rowptr[v+1] = acc; }
    }
    __syncthreads();
    for (int e = tid; e < EE; e += 1024){
        int pos = atomicAdd(&scur[ei[EE+e]], 1);
        g_eid[pos] = e;
    }
    __syncthreads();
    for (int v = tid; v < VV; v += 1024){
        int s = g_rowptr[v], e = g_rowptr[v+1];
        for (int i = s+1; i < e; i++){
            int key = g_eid[i]; int k = i-1;
            while (k >= s && g_eid[k] > key){ g_eid[k+1] = g_eid[k]; k--; }
            g_eid[k+1] = key;
        }
        for (int i = s; i < e; i++){
            int id = g_eid[i];
            g_cols[i] = ei[id];
            g_vals[i] = attr[id];
        }
    }
}

// ---------------- weight folding: Wc = W_g @ Wi  ([64,64]@[64,192]) ----------------
__global__ void k_fold(const float* __restrict__ Wgd, const float* __restrict__ Wid,
                       const float* __restrict__ Wgc, const float* __restrict__ Wic){
    int i = blockIdx.x;          // row 0..63
    int j = threadIdx.x;         // col 0..191
    const float* Wg = (blockIdx.y == 0) ? Wgd : Wgc;
    const float* Wi = (blockIdx.y == 0) ? Wid : Wic;
    float*       Wc = (blockIdx.y == 0) ? g_Wcd : g_Wcc;
    float acc = 0.f;
    #pragma unroll
    for (int k = 0; k < LL; k++) acc += Wg[i*LL + k] * Wi[k*L3 + j];
    Wc[i*L3 + j] = acc;
}

// ---------------- encoder: xe[t,nv,l] = sum_c x[nv,c,t]*W_enc[c,l] + b ----------------
__global__ void k_encode(const float* __restrict__ x, const float* __restrict__ W,
                         const float* __restrict__ b){
    __shared__ float xs[CC*32];
    __shared__ float Ws[CC*LL];
    __shared__ float bs[LL];
    int blk = blockIdx.x;
    int nv = blk / 5;
    int t0 = (blk % 5) * 32;
    int tid = threadIdx.x;
    for (int i = tid; i < CC*32; i += 256){
        int c = i / 32, tl = i % 32, t = t0 + tl;
        xs[c*32 + tl] = (t < TT) ? x[((size_t)nv*CC + c)*TT + t] : 0.f;
    }
    for (int i = tid; i < CC*LL; i += 256) Ws[i] = W[i];
    if (tid < LL) bs[tid] = b[tid];
    __syncthreads();
    int l = tid & 63, tg = tid >> 6;
    for (int tl = tg; tl < 32; tl += 4){
        int t = t0 + tl;
        if (t >= TT) break;
        float acc = bs[l];
        #pragma unroll
        for (int c = 0; c < CC; c++) acc += xs[c*32 + tl] * Ws[c*LL + l];
        g_xe[((size_t)t*NV + nv)*LL + l] = acc;
    }
}

// ---------------- fused gather + GEMM: gi = (S.xe)@Wc + b for all t (one pass) ----------
// grid: TT*NB*16 = 19200 blocks, 384 threads, dyn smem 82688
__global__ void __launch_bounds__(384) k_gather(int pass, const float* __restrict__ bias){
    extern __shared__ float sm[];
    float* Ws  = sm;                 // [64][192]
    float* agg = sm + 64*L3;         // [128][64]
    float* bs  = agg + 128*LL;       // [192]
    const float* Wc = pass ? g_Wcc : g_Wcd;
    int b = blockIdx.x;
    int t   = b >> 7;
    int rem = b & 127;
    int n   = rem >> 4;
    int v0  = (rem & 15) * 128;
    int tid = threadIdx.x;

    for (int i = tid; i < 64*L3; i += 384) Ws[i] = Wc[i];
    if (tid < L3) bs[tid] = bias[tid];

    // gather phase
    const float* xb = g_xe + ((size_t)t*NV + (size_t)n*VV) * LL;
    int lane = tid & 63, rg = tid >> 6;   // rg 0..5
    for (int r = rg; r < 128; r += 6){
        int v = v0 + r;
        int s = g_rowptr[v], e = g_rowptr[v+1];
        float acc = 0.f;
        for (int idx = s; idx < e; idx++)
            acc += xb[(size_t)g_cols[idx]*LL + lane] * g_vals[idx];
        agg[r*LL + lane] = acc;
    }
    __syncthreads();

    // GEMM: agg[128x64] @ Ws[64x192], 8x8 register tiles
    int ct = tid % 24, rt = tid / 24;     // rt 0..15
    int r0 = rt * 8, c0 = ct * 8;
    float acc[8][8];
    #pragma unroll
    for (int i = 0; i < 8; i++)
        #pragma unroll
        for (int j = 0; j < 8; j++) acc[i][j] = bs[c0 + j];

    #pragma unroll 4
    for (int k0 = 0; k0 < 64; k0 += 4){
        float4 a[8];
        #pragma unroll
        for (int i = 0; i < 8; i++) a[i] = *(const float4*)(agg + (r0+i)*LL + k0);
        #pragma unroll
        for (int kk = 0; kk < 4; kk++){
            float4 w0 = *(const float4*)(Ws + (k0+kk)*L3 + c0);
            float4 w1 = *(const float4*)(Ws + (k0+kk)*L3 + c0 + 4);
            #pragma unroll
            for (int i = 0; i < 8; i++){
                float av = (kk==0) ? a[i].x : (kk==1) ? a[i].y : (kk==2) ? a[i].z : a[i].w;
                acc[i][0] += av*w0.x; acc[i][1] += av*w0.y;
                acc[i][2] += av*w0.z; acc[i][3] += av*w0.w;
                acc[i][4] += av*w1.x; acc[i][5] += av*w1.y;
                acc[i][6] += av*w1.z; acc[i][7] += av*w1.w;
            }
        }
    }
    float* outp = g_gi + ((size_t)t*NV + (size_t)n*VV + v0) * L3;
    #pragma unroll
    for (int i = 0; i < 8; i++){
        *(float4*)(outp + (size_t)(r0+i)*L3 + c0)     = make_float4(acc[i][0],acc[i][1],acc[i][2],acc[i][3]);
        *(float4*)(outp + (size_t)(r0+i)*L3 + c0 + 4) = make_float4(acc[i][4],acc[i][5],acc[i][6],acc[i][7]);
    }
}

// ---------------- persistent domain scan: all 150 GRU steps in one kernel ----------------
// grid 256 (64 rows/block), 256 threads, dyn smem 65536 (2 blocks/SM, single wave)
__global__ void __launch_bounds__(256) k_domscan(const float* __restrict__ Wh){
    extern __shared__ float sm[];
    float* Whs = sm;               // [64][192]
    float* hs  = Whs + 64*L3;      // [64][64]
    int tid = threadIdx.x;
    int row0 = blockIdx.x * 64;
    for (int i = tid; i < (64*L3)/4; i += 256) ((float4*)Whs)[i] = ((const float4*)Wh)[i];
    for (int i = tid; i < 64*LL; i += 256) hs[i] = 0.f;
    __syncthreads();

    int ct = tid & 15, rt = tid >> 4;     // 16 colg (4 cols) x 16 rowg (4 rows)
    int c0 = ct * 4, r0 = rt * 4;

    for (int t = 0; t < TT; t++){
        const float* gi = g_gi + ((size_t)t*NV + row0) * L3;
        float az[4][4], ar[4][4], an[4][4];
        #pragma unroll
        for (int i = 0; i < 4; i++)
            #pragma unroll
            for (int j = 0; j < 4; j++){ az[i][j]=0.f; ar[i][j]=0.f; an[i][j]=0.f; }

        #pragma unroll 4
        for (int k0 = 0; k0 < 64; k0 += 4){
            float4 a[4];
            #pragma unroll
            for (int i = 0; i < 4; i++) a[i] = *(const float4*)(hs + (r0+i)*LL + k0);
            #pragma unroll
            for (int kk = 0; kk < 4; kk++){
                float4 wz = *(const float4*)(Whs + (k0+kk)*L3 + c0);
                float4 wr = *(const float4*)(Whs + (k0+kk)*L3 + 64 + c0);
                float4 wn = *(const float4*)(Whs + (k0+kk)*L3 + 128 + c0);
                #pragma unroll
                for (int i = 0; i < 4; i++){
                    float av = (kk==0)?a[i].x:(kk==1)?a[i].y:(kk==2)?a[i].z:a[i].w;
                    az[i][0]+=av*wz.x; az[i][1]+=av*wz.y; az[i][2]+=av*wz.z; az[i][3]+=av*wz.w;
                    ar[i][0]+=av*wr.x; ar[i][1]+=av*wr.y; ar[i][2]+=av*wr.z; ar[i][3]+=av*wr.w;
                    an[i][0]+=av*wn.x; an[i][1]+=av*wn.y; an[i][2]+=av*wn.z; an[i][3]+=av*wn.w;
                }
            }
        }
        __syncthreads();   // all GEMM reads of hs done
        #pragma unroll
        for (int i = 0; i < 4; i++){
            int r = r0 + i;
            float4 giz = *(const float4*)(gi + (size_t)r*L3 + c0);
            float4 gir = *(const float4*)(gi + (size_t)r*L3 + 64 + c0);
            float4 gin = *(const float4*)(gi + (size_t)r*L3 + 128 + c0);
            #pragma unroll
            for (int j = 0; j < 4; j++){
                float gz = (j==0)?giz.x:(j==1)?giz.y:(j==2)?giz.z:giz.w;
                float gr = (j==0)?gir.x:(j==1)?gir.y:(j==2)?gir.z:gir.w;
                float gn = (j==0)?gin.x:(j==1)?gin.y:(j==2)?gin.z:gin.w;
                float z  = sigmf_(az[i][j] + gz);
                float rr = sigmf_(ar[i][j] + gr);
                float nn = tanhf(gn + rr*an[i][j]);
                float hp = hs[r*LL + c0 + j];   // own cell, safe
                hs[r*LL + c0 + j] = (1.f - z)*nn + z*hp;
            }
        }
        __syncthreads();   // writes visible before next GEMM
    }
    for (int i = tid; i < 64*LL; i += 256) g_hd[(size_t)row0*LL + i] = hs[i];
}

// ---------------- domain MLP + cz precompute ----------------
__global__ void k_dommlp(const float* __restrict__ Wd1, const float* __restrict__ bd1,
                         const float* __restrict__ Wd2, const float* __restrict__ bd2,
                         const float* __restrict__ odeW1, const float* __restrict__ odeb1){
    extern __shared__ float sm[];
    float* W1s = sm;            // W_dom1
    float* W2s = W1s + 4096;    // W_dom2
    float* Wzs = W2s + 4096;    // ode_W1 rows 64..127
    float* hds = Wzs + 4096;    // [16][64]
    float* t1s = hds + 1024;
    float* zDs = t1s + 1024;
    float* b1s = zDs + 1024;
    float* b2s = b1s + 64;
    float* bos = b2s + 64;
    int tid = threadIdx.x;
    int row0 = blockIdx.x * 16;
    for (int i = tid; i < 4096; i += 256){ W1s[i] = Wd1[i]; W2s[i] = Wd2[i]; Wzs[i] = odeW1[4096 + i]; }
    for (int i = tid; i < 16*LL; i += 256) hds[i] = g_hd[(size_t)row0*LL + i];
    if (tid < 64){ b1s[tid] = bd1[tid]; b2s[tid] = bd2[tid]; bos[tid] = odeb1[tid]; }
    __syncthreads();
    int j = tid & 63, rg = tid >> 6;
    for (int r = rg; r < 16; r += 4){
        float acc = b1s[j];
        #pragma unroll
        for (int k = 0; k < LL; k++) acc += hds[r*LL + k] * W1s[k*LL + j];
        t1s[r*LL + j] = tanhf(acc);
    }
    __syncthreads();
    for (int r = rg; r < 16; r += 4){
        float acc = b2s[j];
        #pragma unroll
        for (int k = 0; k < LL; k++) acc += t1s[r*LL + k] * W2s[k*LL + j];
        zDs[r*LL + j] = acc;
    }
    __syncthreads();
    for (int r = rg; r < 16; r += 4){
        float acc = bos[j];
        #pragma unroll
        for (int k = 0; k < LL; k++) acc += zDs[r*LL + k] * Wzs[k*LL + j];
        g_cz[(size_t)(row0+r)*LL + j] = acc;
    }
}

// ---------------- persistent correction scan: ODE + GRU, all 149 steps --------------
// grid 128 (128 rows/block), 512 threads, dyn smem 213248 (1 block/SM, single wave)
__global__ void __launch_bounds__(512) k_corrscan(const float* __restrict__ odeW1,
                           const float* __restrict__ odeW2, const float* __restrict__ odeb2,
                           const float* __restrict__ Wh){
    extern __shared__ float sm[];
    float* Whs = sm;               // [64][192]  48K
    float* W1s = Whs + 64*L3;      // [64][64]   16K
    float* W2s = W1s + 4096;       // [64][64]   16K
    float* hs  = W2s + 4096;       // [128][64]  32K
    float* czs = hs  + 128*LL;     // [128][64]  32K
    float* t1s = czs + 128*LL;     // [128][64]  32K
    float* hos = t1s + 128*LL;     // [128][64]  32K
    float* b2s = hos + 128*LL;     // 64
    int tid = threadIdx.x;
    int row0 = blockIdx.x * 128;
    for (int i = tid; i < (64*L3)/4; i += 512) ((float4*)Whs)[i] = ((const float4*)Wh)[i];
    for (int i = tid; i < 1024; i += 512){ ((float4*)W1s)[i] = ((const float4*)odeW1)[i];
                                           ((float4*)W2s)[i] = ((const float4*)odeW2)[i]; }
    for (int i = tid; i < (128*LL)/4; i += 512){
        ((float4*)hs )[i] = ((const float4*)(g_xe + (size_t)row0*LL))[i];   // h0 = xe[0]
        ((float4*)czs)[i] = ((const float4*)(g_cz + (size_t)row0*LL))[i];
    }
    if (tid < 64) b2s[tid] = odeb2[tid];
    __syncthreads();

    // phase1/2 tiling: 2 rows x 8 cols; phase3 tiling: 4 rows x 4 cols (gate-split)
    int p_r0 = (tid >> 3) * 2, p_c0 = (tid & 7) * 8;
    int g_r0 = (tid >> 4) * 4, g_c0 = (tid & 15) * 4;

    for (int t = 1; t < TT; t++){
        // phase1: t1 = tanh(hs @ W1 + cz)
        {
            float acc[2][8];
            #pragma unroll
            for (int i = 0; i < 2; i++){
                float4 cA = *(const float4*)(czs + (p_r0+i)*LL + p_c0);
                float4 cB = *(const float4*)(czs + (p_r0+i)*LL + p_c0 + 4);
                acc[i][0]=cA.x; acc[i][1]=cA.y; acc[i][2]=cA.z; acc[i][3]=cA.w;
                acc[i][4]=cB.x; acc[i][5]=cB.y; acc[i][6]=cB.z; acc[i][7]=cB.w;
            }
            #pragma unroll 4
            for (int k0 = 0; k0 < 64; k0 += 4){
                float4 a0 = *(const float4*)(hs + (p_r0+0)*LL + k0);
                float4 a1 = *(const float4*)(hs + (p_r0+1)*LL + k0);
                #pragma unroll
                for (int kk = 0; kk < 4; kk++){
                    float4 w0 = *(const float4*)(W1s + (k0+kk)*LL + p_c0);
                    float4 w1 = *(const float4*)(W1s + (k0+kk)*LL + p_c0 + 4);
                    float v0 = (kk==0)?a0.x:(kk==1)?a0.y:(kk==2)?a0.z:a0.w;
                    float v1 = (kk==0)?a1.x:(kk==1)?a1.y:(kk==2)?a1.z:a1.w;
                    acc[0][0]+=v0*w0.x; acc[0][1]+=v0*w0.y; acc[0][2]+=v0*w0.z; acc[0][3]+=v0*w0.w;
                    acc[0][4]+=v0*w1.x; acc[0][5]+=v0*w1.y; acc[0][6]+=v0*w1.z; acc[0][7]+=v0*w1.w;
                    acc[1][0]+=v1*w0.x; acc[1][1]+=v1*w0.y; acc[1][2]+=v1*w0.z; acc[1][3]+=v1*w0.w;
                    acc[1][4]+=v1*w1.x; acc[1][5]+=v1*w1.y; acc[1][6]+=v1*w1.z; acc[1][7]+=v1*w1.w;
                }
            }
            #pragma unroll
            for (int i = 0; i < 2; i++)
                #pragma unroll
                for (int j = 0; j < 8; j++) t1s[(p_r0+i)*LL + p_c0 + j] = tanhf(acc[i][j]);
        }
        __syncthreads();
        // phase2: hos = hs + t1 @ W2 + b2
        {
            float acc[2][8];
            #pragma unroll
            for (int i = 0; i < 2; i++)
                #pragma unroll
                for (int j = 0; j < 8; j++) acc[i][j] = b2s[p_c0 + j];
            #pragma unroll 4
            for (int k0 = 0; k0 < 64; k0 += 4){
                float4 a0 = *(const float4*)(t1s + (p_r0+0)*LL + k0);
                float4 a1 = *(const float4*)(t1s + (p_r0+1)*LL + k0);
                #pragma unroll
                for (int kk = 0; kk < 4; kk++){
                    float4 w0 = *(const float4*)(W2s + (k0+kk)*LL + p_c0);
                    float4 w1 = *(const float4*)(W2s + (k0+kk)*LL + p_c0 + 4);
                    float v0 = (kk==0)?a0.x:(kk==1)?a0.y:(kk==2)?a0.z:a0.w;
                    float v1 = (kk==0)?a1.x:(kk==1)?a1.y:(kk==2)?a1.z:a1.w;
                    acc[0][0]+=v0*w0.x; acc[0][1]+=v0*w0.y; acc[0][2]+=v0*w0.z; acc[0][3]+=v0*w0.w;
                    acc[0][4]+=v0*w1.x; acc[0][5]+=v0*w1.y; acc[0][6]+=v0*w1.z; acc[0][7]+=v0*w1.w;
                    acc[1][0]+=v1*w0.x; acc[1][1]+=v1*w0.y; acc[1][2]+=v1*w0.z; acc[1][3]+=v1*w0.w;
                    acc[1][4]+=v1*w1.x; acc[1][5]+=v1*w1.y; acc[1][6]+=v1*w1.z; acc[1][7]+=v1*w1.w;
                }
            }
            #pragma unroll
            for (int i = 0; i < 2; i++)
                #pragma unroll
                for (int j = 0; j < 8; j++)
                    hos[(p_r0+i)*LL + p_c0 + j] = hs[(p_r0+i)*LL + p_c0 + j] + acc[i][j];
        }
        __syncthreads();
        // phase3: GRU gate-split GEMM (reads hos), gates in registers
        {
            const float* gi = g_gi + ((size_t)t*NV + row0) * L3;
            float az[4][4], ar[4][4], an[4][4];
            #pragma unroll
            for (int i = 0; i < 4; i++)
                #pragma unroll
                for (int j = 0; j < 4; j++){ az[i][j]=0.f; ar[i][j]=0.f; an[i][j]=0.f; }
            #pragma unroll 4
            for (int k0 = 0; k0 < 64; k0 += 4){
                float4 a[4];
                #pragma unroll
                for (int i = 0; i < 4; i++) a[i] = *(const float4*)(hos + (g_r0+i)*LL + k0);
                #pragma unroll
                for (int kk = 0; kk < 4; kk++){
                    float4 wz = *(const float4*)(Whs + (k0+kk)*L3 + g_c0);
                    float4 wr = *(const float4*)(Whs + (k0+kk)*L3 + 64 + g_c0);
                    float4 wn = *(const float4*)(Whs + (k0+kk)*L3 + 128 + g_c0);
                    #pragma unroll
                    for (int i = 0; i < 4; i++){
                        float av = (kk==0)?a[i].x:(kk==1)?a[i].y:(kk==2)?a[i].z:a[i].w;
                        az[i][0]+=av*wz.x; az[i][1]+=av*wz.y; az[i][2]+=av*wz.z; az[i][3]+=av*wz.w;
                        ar[i][0]+=av*wr.x; ar[i][1]+=av*wr.y; ar[i][2]+=av*wr.z; ar[i][3]+=av*wr.w;
                        an[i][0]+=av*wn.x; an[i][1]+=av*wn.y; an[i][2]+=av*wn.z; an[i][3]+=av*wn.w;
                    }
                }
            }
            #pragma unroll
            for (int i = 0; i < 4; i++){
                int r = g_r0 + i;
                float4 giz = *(const float4*)(gi + (size_t)r*L3 + g_c0);
                float4 gir = *(const float4*)(gi + (size_t)r*L3 + 64 + g_c0);
                float4 gin = *(const float4*)(gi + (size_t)r*L3 + 128 + g_c0);
                float hn4[4];
                #pragma unroll
                for (int j = 0; j < 4; j++){
                    float gz = (j==0)?giz.x:(j==1)?giz.y:(j==2)?giz.z:giz.w;
                    float gr = (j==0)?gir.x:(j==1)?gir.y:(j==2)?gir.z:gir.w;
                    float gn = (j==0)?gin.x:(j==1)?gin.y:(j==2)?gin.z:gin.w;
                    float z  = sigmf_(az[i][j] + gz);
                    float rr = sigmf_(ar[i][j] + gr);
                    float nn = tanhf(gn + rr*an[i][j]);
                    float ho = hos[r*LL + g_c0 + j];
                    hn4[j] = (1.f - z)*nn + z*ho;
                }
                // hs not read by phase3 GEMM; phase2 readers synced already
                #pragma unroll
                for (int j = 0; j < 4; j++) hs[r*LL + g_c0 + j] = hn4[j];
                *(float4*)(g_xe + ((size_t)t*NV + row0 + r)*LL + g_c0)
                    = make_float4(hn4[0], hn4[1], hn4[2], hn4[3]);
            }
        }
        __syncthreads();   // hs writes visible before next phase1
    }
}

// ---------------- decoder: out[nv,c,t] = z[t,nv,:]@W_dec + b_dec ----------------
__global__ void k_decode(float* __restrict__ out, const float* __restrict__ W,
                         const float* __restrict__ b){
    __shared__ float zs[32*65];
    __shared__ float Ws[LL*CC];
    __shared__ float bs[CC];
    int blk = blockIdx.x;
    int nv = blk / 5;
    int t0 = (blk % 5) * 32;
    int tid = threadIdx.x;
    for (int i = tid; i < 32*LL; i += 256){
        int tl = i >> 6, l = i & 63, t = t0 + tl;
        zs[tl*65 + l] = (t < TT) ? g_xe[((size_t)t*NV + nv)*LL + l] : 0.f;
    }
    for (int i = tid; i < LL*CC; i += 256) Ws[i] = W[i];
    if (tid < CC) bs[tid] = b[tid];
    __syncthreads();
    for (int o = tid; o < 512; o += 256){
        int c = o >> 5, tl = o & 31, t = t0 + tl;
        if (t >= TT) continue;
        float acc = bs[c];
        #pragma unroll
        for (int l = 0; l < LL; l++) acc += zs[tl*65 + l] * Ws[l*CC + c];
        out[((size_t)nv*CC + c)*TT + t] = acc;
    }
}

// ---------------- launch ----------------
extern "C" void kernel_launch(void* const* d_in, const int* in_sizes, int n_in,
                              void* d_out, int out_size){
    const float* x      = (const float*)d_in[0];
    const int*   ei     = (const int*)  d_in[1];
    const float* attr   = (const float*)d_in[2];
    const float* W_enc  = (const float*)d_in[3];
    const float* b_enc  = (const float*)d_in[4];
    const float* W_gd   = (const float*)d_in[5];
    const float* gd_Wi  = (const float*)d_in[6];
    const float* gd_Wh  = (const float*)d_in[7];
    const float* gd_b   = (const float*)d_in[8];
    const float* W_dom1 = (const float*)d_in[9];
    const float* b_dom1 = (const float*)d_in[10];
    const float* W_dom2 = (const float*)d_in[11];
    const float* b_dom2 = (const float*)d_in[12];
    const float* ode_W1 = (const float*)d_in[13];
    const float* ode_b1 = (const float*)d_in[14];
    const float* ode_W2 = (const float*)d_in[15];
    const float* ode_b2 = (const float*)d_in[16];
    const float* W_gc   = (const float*)d_in[17];
    const float* gc_Wi  = (const float*)d_in[18];
    const float* gc_Wh  = (const float*)d_in[19];
    const float* gc_b   = (const float*)d_in[20];
    const float* W_dec  = (const float*)d_in[21];
    const float* b_dec  = (const float*)d_in[22];
    float* out = (float*)d_out;

    const int SM_GATHER = (64*L3 + 128*LL + L3) * 4;                          // 82688
    const int SM_DOMS   = (64*L3 + 64*LL) * 4;                                // 65536
    const int SM_CORRS  = (64*L3 + 4096 + 4096 + 4*128*LL + 64) * 4;          // 213248
    const int SM_MLP    = (3*4096 + 3*1024 + 3*64) * 4;                       // 62208

    cudaFuncSetAttribute(k_gather,   cudaFuncAttributeMaxDynamicSharedMemorySize, SM_GATHER);
    cudaFuncSetAttribute(k_domscan,  cudaFuncAttributeMaxDynamicSharedMemorySize, SM_DOMS);
    cudaFuncSetAttribute(k_corrscan, cudaFuncAttributeMaxDynamicSharedMemorySize, SM_CORRS);
    cudaFuncSetAttribute(k_dommlp,   cudaFuncAttributeMaxDynamicSharedMemorySize, SM_MLP);

    // 1: CSR build (one block, deterministic)
    k_csr <<<1, 1024>>>(ei, attr);
    // 2: weight folding
    k_fold<<<dim3(64, 2), L3>>>(W_gd, gd_Wi, W_gc, gc_Wi);
    // 3: encoder
    k_encode<<<NV*5, 256>>>(x, W_enc, b_enc);
    // 4: gi for domain GRU  (ncu capture slot)
    k_gather<<<TT*NB*16, 384, SM_GATHER>>>(0, gd_b);
    // 5: persistent domain scan (150 steps, one launch)
    k_domscan<<<NV/64, 256, SM_DOMS>>>(gd_Wh);
    // 6: domain MLP + cz
    k_dommlp<<<NV/16, 256, SM_MLP>>>(W_dom1, b_dom1, W_dom2, b_dom2, ode_W1, ode_b1);
    // 7: gi for correction GRU (reuses g_gi)
    k_gather<<<TT*NB*16, 384, SM_GATHER>>>(1, gc_b);
    // 8: persistent correction scan (149 steps, one launch)
    k_corrscan<<<NV/128, 512, SM_CORRS>>>(ode_W1, ode_W2, ode_b2, gc_Wh);
    // 9: decoder
    k_decode<<<NV*5, 256>>>(out, W_dec, b_dec);
}

// round 12
// speedup vs baseline: 1.6389x; 1.2988x over previous
#include <cuda_runtime.h>
#include <math.h>

#define TT 150
#define NB 8
#define VV 2048
#define CC 16
#define LL 64
#define L3 192
#define EE 32768
#define NV (NB*VV)   // 16384

typedef unsigned long long u64;

// ---------------- static device scratch (~3.15 GB .bss — under aarch64 adrp reach) ----
__device__ float g_xe [(size_t)TT*NV*LL];   // encoder output; later overwritten with z
__device__ float g_agg[(size_t)TT*NV*LL];   // gathered S.xe (pass-independent!)
__device__ float g_gi [(size_t)TT*NV*L3];   // gi buffer, reused: pass1=domain, pass2=correction
__device__ float g_hd [NV*LL];              // domain hidden (final)
__device__ float g_cz [NV*LL];              // z_D @ ode_W1[64:128] + ode_b1
__device__ float g_Wcd[LL*L3];              // W_gd @ gd_Wi
__device__ float g_Wcc[LL*L3];              // W_gc @ gc_Wi
__device__ int   g_rowptr[VV+1];
__device__ int   g_eid [EE];
__device__ int   g_cols[EE];
__device__ float g_vals[EE];

__device__ __forceinline__ float sigmf_(float x){ return 1.f/(1.f+expf(-x)); }

// packed fp32x2 FMA (Blackwell FFMA2 — doubles fp32 FMA throughput, bitwise == scalar)
__device__ __forceinline__ u64 f2fma(u64 a, u64 b, u64 c){
    u64 d; asm("fma.rn.f32x2 %0, %1, %2, %3;" : "=l"(d) : "l"(a), "l"(b), "l"(c)); return d;
}
__device__ __forceinline__ u64 f2dup(float x){
    u64 d; asm("mov.b64 %0, {%1, %2};" : "=l"(d) : "f"(x), "f"(x)); return d;
}
__device__ __forceinline__ float2 f2unpk(u64 v){
    float2 r; asm("mov.b64 {%0, %1}, %2;" : "=f"(r.x), "=f"(r.y) : "l"(v)); return r;
}

// ---------------- CSR build: ONE block, deterministic (rows sorted by edge id) --------
__global__ void __launch_bounds__(1024) k_csr(const int* __restrict__ ei,
                                              const float* __restrict__ attr){
    __shared__ int sdeg[VV];
    __shared__ int scur[VV];
    int tid = threadIdx.x;
    for (int v = tid; v < VV; v += 1024) sdeg[v] = 0;
    __syncthreads();
    for (int e = tid; e < EE; e += 1024) atomicAdd(&sdeg[ei[EE+e]], 1);
    __syncthreads();
    if (tid == 0){
        int acc = 0;
        g_rowptr[0] = 0;
        for (int v = 0; v < VV; v++){ scur[v] = acc; acc += sdeg[v]; g_rowptr[v+1] = acc; }
    }
    __syncthreads();
    for (int e = tid; e < EE; e += 1024){
        int pos = atomicAdd(&scur[ei[EE+e]], 1);
        g_eid[pos] = e;
    }
    __syncthreads();
    for (int v = tid; v < VV; v += 1024){
        int s = g_rowptr[v], e = g_rowptr[v+1];
        for (int i = s+1; i < e; i++){
            int key = g_eid[i]; int k = i-1;
            while (k >= s && g_eid[k] > key){ g_eid[k+1] = g_eid[k]; k--; }
            g_eid[k+1] = key;
        }
        for (int i = s; i < e; i++){
            int id = g_eid[i];
            g_cols[i] = ei[id];
            g_vals[i] = attr[id];
        }
    }
}

// ---------------- weight folding: Wc = W_g @ Wi  ([64,64]@[64,192]) ----------------
__global__ void k_fold(const float* __restrict__ Wgd, const float* __restrict__ Wid,
                       const float* __restrict__ Wgc, const float* __restrict__ Wic){
    int i = blockIdx.x;
    int j = threadIdx.x;
    const float* Wg = (blockIdx.y == 0) ? Wgd : Wgc;
    const float* Wi = (blockIdx.y == 0) ? Wid : Wic;
    float*       Wc = (blockIdx.y == 0) ? g_Wcd : g_Wcc;
    float acc = 0.f;
    #pragma unroll
    for (int k = 0; k < LL; k++) acc += Wg[i*LL + k] * Wi[k*L3 + j];
    Wc[i*L3 + j] = acc;
}

// ---------------- encoder: xe[t,nv,l] = sum_c x[nv,c,t]*W_enc[c,l] + b ----------------
__global__ void k_encode(const float* __restrict__ x, const float* __restrict__ W,
                         const float* __restrict__ b){
    __shared__ float xs[CC*32];
    __shared__ float Ws[CC*LL];
    __shared__ float bs[LL];
    int blk = blockIdx.x;
    int nv = blk / 5;
    int t0 = (blk % 5) * 32;
    int tid = threadIdx.x;
    for (int i = tid; i < CC*32; i += 256){
        int c = i / 32, tl = i % 32, t = t0 + tl;
        xs[c*32 + tl] = (t < TT) ? x[((size_t)nv*CC + c)*TT + t] : 0.f;
    }
    for (int i = tid; i < CC*LL; i += 256) Ws[i] = W[i];
    if (tid < LL) bs[tid] = b[tid];
    __syncthreads();
    int l = tid & 63, tg = tid >> 6;
    for (int tl = tg; tl < 32; tl += 4){
        int t = t0 + tl;
        if (t >= TT) break;
        float acc = bs[l];
        #pragma unroll
        for (int c = 0; c < CC; c++) acc += xs[c*32 + tl] * Ws[c*LL + l];
        g_xe[((size_t)t*NV + nv)*LL + l] = acc;
    }
}

// ---------------- gather only (ONCE): agg[t,row,:] = sum_e attr*xe[t,src,:] ----------
// grid TT*128 = 19200, 256 threads, no smem — low regs, high occupancy
__global__ void __launch_bounds__(256) k_agg(){
    int b = blockIdx.x;
    int t   = b >> 7;
    int rem = b & 127;
    int n   = rem >> 4;
    int v0  = (rem & 15) * 128;
    int tid = threadIdx.x;
    const float* xb = g_xe  + ((size_t)t*NV + (size_t)n*VV) * LL;
    float*       ob = g_agg + ((size_t)t*NV + (size_t)n*VV + v0) * LL;
    int lane = tid & 63, rg = tid >> 6;   // rg 0..3
    for (int r = rg; r < 128; r += 4){
        int v = v0 + r;
        int s = g_rowptr[v], e = g_rowptr[v+1];
        float acc = 0.f;
        for (int idx = s; idx < e; idx++)
            acc += xb[(size_t)g_cols[idx]*LL + lane] * g_vals[idx];
        ob[(size_t)r*LL + lane] = acc;
    }
}

// ---------------- dense GEMM: gi = agg @ Wc + b (f32x2, 8x8 tiles) --------------------
// grid TT*NV/128 = 19200, 384 threads, dyn smem 82688
__global__ void __launch_bounds__(384) k_gemm(int pass, const float* __restrict__ bias){
    extern __shared__ float sm[];
    float* Ws = sm;            // [64][192]
    float* As = sm + 64*L3;    // [128][64]
    float* bs = As + 128*LL;   // [192]
    const float* Wc = pass ? g_Wcc : g_Wcd;
    size_t row0 = (size_t)blockIdx.x * 128;
    int tid = threadIdx.x;
    for (int i = tid; i < (64*L3)/4; i += 384) ((float4*)Ws)[i] = ((const float4*)Wc)[i];
    for (int i = tid; i < (128*LL)/4; i += 384) ((float4*)As)[i] = ((const float4*)(g_agg + row0*LL))[i];
    if (tid < L3) bs[tid] = bias[tid];
    __syncthreads();
    int ct = tid % 24, rt = tid / 24;   // 16 rowg x 24 colg
    int r0 = rt * 8, c0 = ct * 8;
    u64 acc[8][4];
    {
        const u64* bp = (const u64*)(bs + c0);
        u64 b0 = bp[0], b1 = bp[1], b2 = bp[2], b3 = bp[3];
        #pragma unroll
        for (int i = 0; i < 8; i++){ acc[i][0]=b0; acc[i][1]=b1; acc[i][2]=b2; acc[i][3]=b3; }
    }
    #pragma unroll 4
    for (int k0 = 0; k0 < 64; k0 += 4){
        float4 a[8];
        #pragma unroll
        for (int i = 0; i < 8; i++) a[i] = *(const float4*)(As + (r0+i)*LL + k0);
        #pragma unroll
        for (int kk = 0; kk < 4; kk++){
            const u64* wp = (const u64*)(Ws + (k0+kk)*L3 + c0);
            u64 w0 = wp[0], w1 = wp[1], w2 = wp[2], w3 = wp[3];
            #pragma unroll
            for (int i = 0; i < 8; i++){
                float av = (kk==0)?a[i].x:(kk==1)?a[i].y:(kk==2)?a[i].z:a[i].w;
                u64 ad = f2dup(av);
                acc[i][0] = f2fma(ad, w0, acc[i][0]);
                acc[i][1] = f2fma(ad, w1, acc[i][1]);
                acc[i][2] = f2fma(ad, w2, acc[i][2]);
                acc[i][3] = f2fma(ad, w3, acc[i][3]);
            }
        }
    }
    float* outp = g_gi + row0 * L3;
    #pragma unroll
    for (int i = 0; i < 8; i++){
        u64* op = (u64*)(outp + (size_t)(r0+i)*L3 + c0);
        op[0]=acc[i][0]; op[1]=acc[i][1]; op[2]=acc[i][2]; op[3]=acc[i][3];
    }
}

// ---------------- persistent domain scan: all 150 GRU steps, f32x2 GEMM ---------------
// grid 256 (64 rows/block), 256 threads, dyn smem 65536
__global__ void __launch_bounds__(256) k_domscan(const float* __restrict__ Wh){
    extern __shared__ float sm[];
    float* Whs = sm;               // [64][192]
    float* hs  = Whs + 64*L3;      // [64][64]
    int tid = threadIdx.x;
    int row0 = blockIdx.x * 64;
    for (int i = tid; i < (64*L3)/4; i += 256) ((float4*)Whs)[i] = ((const float4*)Wh)[i];
    for (int i = tid; i < 64*LL; i += 256) hs[i] = 0.f;
    __syncthreads();

    int c0 = (tid & 15) * 4, r0 = (tid >> 4) * 4;

    for (int t = 0; t < TT; t++){
        const float* gi = g_gi + ((size_t)t*NV + row0) * L3;
        u64 az[4][2], ar[4][2], an[4][2];
        #pragma unroll
        for (int i = 0; i < 4; i++){
            az[i][0]=0ull; az[i][1]=0ull; ar[i][0]=0ull; ar[i][1]=0ull; an[i][0]=0ull; an[i][1]=0ull;
        }
        #pragma unroll 4
        for (int k0 = 0; k0 < 64; k0 += 4){
            float4 a[4];
            #pragma unroll
            for (int i = 0; i < 4; i++) a[i] = *(const float4*)(hs + (r0+i)*LL + k0);
            #pragma unroll
            for (int kk = 0; kk < 4; kk++){
                ulonglong2 wz = *(const ulonglong2*)(Whs + (k0+kk)*L3 + c0);
                ulonglong2 wr = *(const ulonglong2*)(Whs + (k0+kk)*L3 + 64 + c0);
                ulonglong2 wn = *(const ulonglong2*)(Whs + (k0+kk)*L3 + 128 + c0);
                #pragma unroll
                for (int i = 0; i < 4; i++){
                    float av = (kk==0)?a[i].x:(kk==1)?a[i].y:(kk==2)?a[i].z:a[i].w;
                    u64 ad = f2dup(av);
                    az[i][0]=f2fma(ad,wz.x,az[i][0]); az[i][1]=f2fma(ad,wz.y,az[i][1]);
                    ar[i][0]=f2fma(ad,wr.x,ar[i][0]); ar[i][1]=f2fma(ad,wr.y,ar[i][1]);
                    an[i][0]=f2fma(ad,wn.x,an[i][0]); an[i][1]=f2fma(ad,wn.y,an[i][1]);
                }
            }
        }
        __syncthreads();   // all GEMM reads of hs done
        #pragma unroll
        for (int i = 0; i < 4; i++){
            int r = r0 + i;
            float4 giz = *(const float4*)(gi + (size_t)r*L3 + c0);
            float4 gir = *(const float4*)(gi + (size_t)r*L3 + 64 + c0);
            float4 gin = *(const float4*)(gi + (size_t)r*L3 + 128 + c0);
            float2 vz0 = f2unpk(az[i][0]), vz1 = f2unpk(az[i][1]);
            float2 vr0 = f2unpk(ar[i][0]), vr1 = f2unpk(ar[i][1]);
            float2 vn0 = f2unpk(an[i][0]), vn1 = f2unpk(an[i][1]);
            float zz[4] = { vz0.x+giz.x, vz0.y+giz.y, vz1.x+giz.z, vz1.y+giz.w };
            float rr[4] = { vr0.x+gir.x, vr0.y+gir.y, vr1.x+gir.z, vr1.y+gir.w };
            float gn[4] = { gin.x, gin.y, gin.z, gin.w };
            float hv[4] = { vn0.x, vn0.y, vn1.x, vn1.y };
            #pragma unroll
            for (int j = 0; j < 4; j++){
                float z  = sigmf_(zz[j]);
                float rg = sigmf_(rr[j]);
                float nn = tanhf(gn[j] + rg*hv[j]);
                float hp = hs[r*LL + c0 + j];
                hs[r*LL + c0 + j] = (1.f - z)*nn + z*hp;
            }
        }
        __syncthreads();
    }
    for (int i = tid; i < 64*LL; i += 256) g_hd[(size_t)row0*LL + i] = hs[i];
}

// ---------------- domain MLP + cz precompute ----------------
__global__ void k_dommlp(const float* __restrict__ Wd1, const float* __restrict__ bd1,
                         const float* __restrict__ Wd2, const float* __restrict__ bd2,
                         const float* __restrict__ odeW1, const float* __restrict__ odeb1){
    extern __shared__ float sm[];
    float* W1s = sm;
    float* W2s = W1s + 4096;
    float* Wzs = W2s + 4096;
    float* hds = Wzs + 4096;
    float* t1s = hds + 1024;
    float* zDs = t1s + 1024;
    float* b1s = zDs + 1024;
    float* b2s = b1s + 64;
    float* bos = b2s + 64;
    int tid = threadIdx.x;
    int row0 = blockIdx.x * 16;
    for (int i = tid; i < 4096; i += 256){ W1s[i] = Wd1[i]; W2s[i] = Wd2[i]; Wzs[i] = odeW1[4096 + i]; }
    for (int i = tid; i < 16*LL; i += 256) hds[i] = g_hd[(size_t)row0*LL + i];
    if (tid < 64){ b1s[tid] = bd1[tid]; b2s[tid] = bd2[tid]; bos[tid] = odeb1[tid]; }
    __syncthreads();
    int j = tid & 63, rg = tid >> 6;
    for (int r = rg; r < 16; r += 4){
        float acc = b1s[j];
        #pragma unroll
        for (int k = 0; k < LL; k++) acc += hds[r*LL + k] * W1s[k*LL + j];
        t1s[r*LL + j] = tanhf(acc);
    }
    __syncthreads();
    for (int r = rg; r < 16; r += 4){
        float acc = b2s[j];
        #pragma unroll
        for (int k = 0; k < LL; k++) acc += t1s[r*LL + k] * W2s[k*LL + j];
        zDs[r*LL + j] = acc;
    }
    __syncthreads();
    for (int r = rg; r < 16; r += 4){
        float acc = bos[j];
        #pragma unroll
        for (int k = 0; k < LL; k++) acc += zDs[r*LL + k] * Wzs[k*LL + j];
        g_cz[(size_t)(row0+r)*LL + j] = acc;
    }
}

// ---------------- persistent correction scan: ODE + GRU, 149 steps, f32x2 -------------
// grid 128 (128 rows/block), 512 threads, dyn smem 213248
__global__ void __launch_bounds__(512) k_corrscan(const float* __restrict__ odeW1,
                           const float* __restrict__ odeW2, const float* __restrict__ odeb2,
                           const float* __restrict__ Wh){
    extern __shared__ float sm[];
    float* Whs = sm;               // [64][192]
    float* W1s = Whs + 64*L3;      // [64][64]
    float* W2s = W1s + 4096;       // [64][64]
    float* hs  = W2s + 4096;       // [128][64]
    float* czs = hs  + 128*LL;     // [128][64]
    float* t1s = czs + 128*LL;     // [128][64]
    float* hos = t1s + 128*LL;     // [128][64]
    float* b2s = hos + 128*LL;     // 64
    int tid = threadIdx.x;
    int row0 = blockIdx.x * 128;
    for (int i = tid; i < (64*L3)/4; i += 512) ((float4*)Whs)[i] = ((const float4*)Wh)[i];
    for (int i = tid; i < 1024; i += 512){ ((float4*)W1s)[i] = ((const float4*)odeW1)[i];
                                           ((float4*)W2s)[i] = ((const float4*)odeW2)[i]; }
    for (int i = tid; i < (128*LL)/4; i += 512){
        ((float4*)hs )[i] = ((const float4*)(g_xe + (size_t)row0*LL))[i];   // h0 = xe[0]
        ((float4*)czs)[i] = ((const float4*)(g_cz + (size_t)row0*LL))[i];
    }
    if (tid < 64) b2s[tid] = odeb2[tid];
    __syncthreads();

    int p_r0 = (tid >> 3) * 2, p_c0 = (tid & 7) * 8;    // phase1/2: 2 rows x 8 cols
    int g_r0 = (tid >> 4) * 4, g_c0 = (tid & 15) * 4;   // phase3:   4 rows x 4 cols

    for (int t = 1; t < TT; t++){
        // phase1: t1 = tanh(hs @ W1 + cz)
        {
            u64 acc[2][4];
            #pragma unroll
            for (int i = 0; i < 2; i++){
                const u64* cp = (const u64*)(czs + (p_r0+i)*LL + p_c0);
                acc[i][0]=cp[0]; acc[i][1]=cp[1]; acc[i][2]=cp[2]; acc[i][3]=cp[3];
            }
            #pragma unroll 4
            for (int k0 = 0; k0 < 64; k0 += 4){
                float4 a0 = *(const float4*)(hs + (p_r0+0)*LL + k0);
                float4 a1 = *(const float4*)(hs + (p_r0+1)*LL + k0);
                #pragma unroll
                for (int kk = 0; kk < 4; kk++){
                    const u64* wp = (const u64*)(W1s + (k0+kk)*LL + p_c0);
                    u64 w0=wp[0], w1=wp[1], w2=wp[2], w3=wp[3];
                    float v0 = (kk==0)?a0.x:(kk==1)?a0.y:(kk==2)?a0.z:a0.w;
                    float v1 = (kk==0)?a1.x:(kk==1)?a1.y:(kk==2)?a1.z:a1.w;
                    u64 d0 = f2dup(v0), d1 = f2dup(v1);
                    acc[0][0]=f2fma(d0,w0,acc[0][0]); acc[0][1]=f2fma(d0,w1,acc[0][1]);
                    acc[0][2]=f2fma(d0,w2,acc[0][2]); acc[0][3]=f2fma(d0,w3,acc[0][3]);
                    acc[1][0]=f2fma(d1,w0,acc[1][0]); acc[1][1]=f2fma(d1,w1,acc[1][1]);
                    acc[1][2]=f2fma(d1,w2,acc[1][2]); acc[1][3]=f2fma(d1,w3,acc[1][3]);
                }
            }
            #pragma unroll
            for (int i = 0; i < 2; i++)
                #pragma unroll
                for (int p = 0; p < 4; p++){
                    float2 v = f2unpk(acc[i][p]);
                    t1s[(p_r0+i)*LL + p_c0 + 2*p    ] = tanhf(v.x);
                    t1s[(p_r0+i)*LL + p_c0 + 2*p + 1] = tanhf(v.y);
                }
        }
        __syncthreads();
        // phase2: hos = hs + t1 @ W2 + b2
        {
            u64 acc[2][4];
            {
                const u64* bp = (const u64*)(b2s + p_c0);
                u64 b0=bp[0], b1=bp[1], b2=bp[2], b3=bp[3];
                acc[0][0]=b0; acc[0][1]=b1; acc[0][2]=b2; acc[0][3]=b3;
                acc[1][0]=b0; acc[1][1]=b1; acc[1][2]=b2; acc[1][3]=b3;
            }
            #pragma unroll 4
            for (int k0 = 0; k0 < 64; k0 += 4){
                float4 a0 = *(const float4*)(t1s + (p_r0+0)*LL + k0);
                float4 a1 = *(const float4*)(t1s + (p_r0+1)*LL + k0);
                #pragma unroll
                for (int kk = 0; kk < 4; kk++){
                    const u64* wp = (const u64*)(W2s + (k0+kk)*LL + p_c0);
                    u64 w0=wp[0], w1=wp[1], w2=wp[2], w3=wp[3];
                    float v0 = (kk==0)?a0.x:(kk==1)?a0.y:(kk==2)?a0.z:a0.w;
                    float v1 = (kk==0)?a1.x:(kk==1)?a1.y:(kk==2)?a1.z:a1.w;
                    u64 d0 = f2dup(v0), d1 = f2dup(v1);
                    acc[0][0]=f2fma(d0,w0,acc[0][0]); acc[0][1]=f2fma(d0,w1,acc[0][1]);
                    acc[0][2]=f2fma(d0,w2,acc[0][2]); acc[0][3]=f2fma(d0,w3,acc[0][3]);
                    acc[1][0]=f2fma(d1,w0,acc[1][0]); acc[1][1]=f2fma(d1,w1,acc[1][1]);
                    acc[1][2]=f2fma(d1,w2,acc[1][2]); acc[1][3]=f2fma(d1,w3,acc[1][3]);
                }
            }
            #pragma unroll
            for (int i = 0; i < 2; i++)
                #pragma unroll
                for (int p = 0; p < 4; p++){
                    float2 v = f2unpk(acc[i][p]);
                    int base = (p_r0+i)*LL + p_c0 + 2*p;
                    hos[base    ] = hs[base    ] + v.x;
                    hos[base + 1] = hs[base + 1] + v.y;
                }
        }
        __syncthreads();
        // phase3: GRU gate-split GEMM on hos, gates in registers
        {
            const float* gi = g_gi + ((size_t)t*NV + row0) * L3;
            u64 az[4][2], ar[4][2], an[4][2];
            #pragma unroll
            for (int i = 0; i < 4; i++){
                az[i][0]=0ull; az[i][1]=0ull; ar[i][0]=0ull; ar[i][1]=0ull; an[i][0]=0ull; an[i][1]=0ull;
            }
            #pragma unroll 4
            for (int k0 = 0; k0 < 64; k0 += 4){
                float4 a[4];
                #pragma unroll
                for (int i = 0; i < 4; i++) a[i] = *(const float4*)(hos + (g_r0+i)*LL + k0);
                #pragma unroll
                for (int kk = 0; kk < 4; kk++){
                    ulonglong2 wz = *(const ulonglong2*)(Whs + (k0+kk)*L3 + g_c0);
                    ulonglong2 wr = *(const ulonglong2*)(Whs + (k0+kk)*L3 + 64 + g_c0);
                    ulonglong2 wn = *(const ulonglong2*)(Whs + (k0+kk)*L3 + 128 + g_c0);
                    #pragma unroll
                    for (int i = 0; i < 4; i++){
                        float av = (kk==0)?a[i].x:(kk==1)?a[i].y:(kk==2)?a[i].z:a[i].w;
                        u64 ad = f2dup(av);
                        az[i][0]=f2fma(ad,wz.x,az[i][0]); az[i][1]=f2fma(ad,wz.y,az[i][1]);
                        ar[i][0]=f2fma(ad,wr.x,ar[i][0]); ar[i][1]=f2fma(ad,wr.y,ar[i][1]);
                        an[i][0]=f2fma(ad,wn.x,an[i][0]); an[i][1]=f2fma(ad,wn.y,an[i][1]);
                    }
                }
            }
            #pragma unroll
            for (int i = 0; i < 4; i++){
                int r = g_r0 + i;
                float4 giz = *(const float4*)(gi + (size_t)r*L3 + g_c0);
                float4 gir = *(const float4*)(gi + (size_t)r*L3 + 64 + g_c0);
                float4 gin = *(const float4*)(gi + (size_t)r*L3 + 128 + g_c0);
                float2 vz0 = f2unpk(az[i][0]), vz1 = f2unpk(az[i][1]);
                float2 vr0 = f2unpk(ar[i][0]), vr1 = f2unpk(ar[i][1]);
                float2 vn0 = f2unpk(an[i][0]), vn1 = f2unpk(an[i][1]);
                float zz[4] = { vz0.x+giz.x, vz0.y+giz.y, vz1.x+giz.z, vz1.y+giz.w };
                float rr[4] = { vr0.x+gir.x, vr0.y+gir.y, vr1.x+gir.z, vr1.y+gir.w };
                float gn[4] = { gin.x, gin.y, gin.z, gin.w };
                float hv[4] = { vn0.x, vn0.y, vn1.x, vn1.y };
                float hn4[4];
                #pragma unroll
                for (int j = 0; j < 4; j++){
                    float z  = sigmf_(zz[j]);
                    float rg = sigmf_(rr[j]);
                    float nn = tanhf(gn[j] + rg*hv[j]);
                    float ho = hos[r*LL + g_c0 + j];
                    hn4[j] = (1.f - z)*nn + z*ho;
                }
                #pragma unroll
                for (int j = 0; j < 4; j++) hs[r*LL + g_c0 + j] = hn4[j];
                *(float4*)(g_xe + ((size_t)t*NV + row0 + r)*LL + g_c0)
                    = make_float4(hn4[0], hn4[1], hn4[2], hn4[3]);
            }
        }
        __syncthreads();
    }
}

// ---------------- decoder: out[nv,c,t] = z[t,nv,:]@W_dec + b_dec ----------------
__global__ void k_decode(float* __restrict__ out, const float* __restrict__ W,
                         const float* __restrict__ b){
    __shared__ float zs[32*65];
    __shared__ float Ws[LL*CC];
    __shared__ float bs[CC];
    int blk = blockIdx.x;
    int nv = blk / 5;
    int t0 = (blk % 5) * 32;
    int tid = threadIdx.x;
    for (int i = tid; i < 32*LL; i += 256){
        int tl = i >> 6, l = i & 63, t = t0 + tl;
        zs[tl*65 + l] = (t < TT) ? g_xe[((size_t)t*NV + nv)*LL + l] : 0.f;
    }
    for (int i = tid; i < LL*CC; i += 256) Ws[i] = W[i];
    if (tid < CC) bs[tid] = b[tid];
    __syncthreads();
    for (int o = tid; o < 512; o += 256){
        int c = o >> 5, tl = o & 31, t = t0 + tl;
        if (t >= TT) continue;
        float acc = bs[c];
        #pragma unroll
        for (int l = 0; l < LL; l++) acc += zs[tl*65 + l] * Ws[l*CC + c];
        out[((size_t)nv*CC + c)*TT + t] = acc;
    }
}

// ---------------- launch ----------------
extern "C" void kernel_launch(void* const* d_in, const int* in_sizes, int n_in,
                              void* d_out, int out_size){
    const float* x      = (const float*)d_in[0];
    const int*   ei     = (const int*)  d_in[1];
    const float* attr   = (const float*)d_in[2];
    const float* W_enc  = (const float*)d_in[3];
    const float* b_enc  = (const float*)d_in[4];
    const float* W_gd   = (const float*)d_in[5];
    const float* gd_Wi  = (const float*)d_in[6];
    const float* gd_Wh  = (const float*)d_in[7];
    const float* gd_b   = (const float*)d_in[8];
    const float* W_dom1 = (const float*)d_in[9];
    const float* b_dom1 = (const float*)d_in[10];
    const float* W_dom2 = (const float*)d_in[11];
    const float* b_dom2 = (const float*)d_in[12];
    const float* ode_W1 = (const float*)d_in[13];
    const float* ode_b1 = (const float*)d_in[14];
    const float* ode_W2 = (const float*)d_in[15];
    const float* ode_b2 = (const float*)d_in[16];
    const float* W_gc   = (const float*)d_in[17];
    const float* gc_Wi  = (const float*)d_in[18];
    const float* gc_Wh  = (const float*)d_in[19];
    const float* gc_b   = (const float*)d_in[20];
    const float* W_dec  = (const float*)d_in[21];
    const float* b_dec  = (const float*)d_in[22];
    float* out = (float*)d_out;

    const int SM_GEMM  = (64*L3 + 128*LL + L3) * 4;                           // 82688
    const int SM_DOMS  = (64*L3 + 64*LL) * 4;                                 // 65536
    const int SM_CORRS = (64*L3 + 4096 + 4096 + 4*128*LL + 64) * 4;           // 213248
    const int SM_MLP   = (3*4096 + 3*1024 + 3*64) * 4;                        // 62208

    cudaFuncSetAttribute(k_gemm,     cudaFuncAttributeMaxDynamicSharedMemorySize, SM_GEMM);
    cudaFuncSetAttribute(k_domscan,  cudaFuncAttributeMaxDynamicSharedMemorySize, SM_DOMS);
    cudaFuncSetAttribute(k_corrscan, cudaFuncAttributeMaxDynamicSharedMemorySize, SM_CORRS);
    cudaFuncSetAttribute(k_dommlp,   cudaFuncAttributeMaxDynamicSharedMemorySize, SM_MLP);

    // 1: weight folding
    k_fold<<<dim3(64, 2), L3>>>(W_gd, gd_Wi, W_gc, gc_Wi);
    // 2: encoder
    k_encode<<<NV*5, 256>>>(x, W_enc, b_enc);
    // 3: CSR build (one block, deterministic)
    k_csr <<<1, 1024>>>(ei, attr);
    // 4: gather ONCE (pass-independent)
    k_agg <<<TT*128, 256>>>();
    // 5: dense GEMM pass 0 (domain gi)
    k_gemm<<<TT*NV/128, 384, SM_GEMM>>>(0, gd_b);
    // 6: persistent domain scan
    k_domscan<<<NV/64, 256, SM_DOMS>>>(gd_Wh);
    // 7: domain MLP + cz
    k_dommlp<<<NV/16, 256, SM_MLP>>>(W_dom1, b_dom1, W_dom2, b_dom2, ode_W1, ode_b1);
    // 8: dense GEMM pass 1 (correction gi, reuses g_gi)
    k_gemm<<<TT*NV/128, 384, SM_GEMM>>>(1, gc_b);
    // 9: persistent correction scan
    k_corrscan<<<NV/128, 512, SM_CORRS>>>(ode_W1, ode_W2, ode_b2, gc_Wh);
    // 10: decoder
    k_decode<<<NV*5, 256>>>(out, W_dec, b_dec);
}

// round 13
// speedup vs baseline: 1.9815x; 1.2091x over previous
#include <cuda_runtime.h>
#include <math.h>

#define TT 150
#define NB 8
#define VV 2048
#define CC 16
#define LL 64
#define L3 192
#define EE 32768
#define NV (NB*VV)   // 16384

typedef unsigned long long u64;

// ---------------- static device scratch (~1.3 GB .bss) ----------------
__device__ float g_xe [(size_t)TT*NV*LL];   // encoder output; later overwritten with z
__device__ float g_agg[(size_t)TT*NV*LL];   // gathered S.xe (pass-independent)
__device__ float g_hd [NV*LL];              // domain hidden (final)
__device__ float g_cz [NV*LL];              // z_D @ ode_W1[64:128] + ode_b1
__device__ float g_Wcd[LL*L3];              // W_gd @ gd_Wi
__device__ float g_Wcc[LL*L3];              // W_gc @ gc_Wi
__device__ int   g_rowptr[VV+1];
__device__ int   g_eid [EE];
__device__ int   g_cols[EE];
__device__ float g_vals[EE];

__device__ __forceinline__ float sigmf_(float x){ return 1.f/(1.f+expf(-x)); }

// packed fp32x2 FMA (Blackwell FFMA2 — 2x fp32 FMA throughput, bitwise == scalar)
__device__ __forceinline__ u64 f2fma(u64 a, u64 b, u64 c){
    u64 d; asm("fma.rn.f32x2 %0, %1, %2, %3;" : "=l"(d) : "l"(a), "l"(b), "l"(c)); return d;
}
__device__ __forceinline__ u64 f2dup(float x){
    u64 d; asm("mov.b64 %0, {%1, %2};" : "=l"(d) : "f"(x), "f"(x)); return d;
}
__device__ __forceinline__ float2 f2unpk(u64 v){
    float2 r; asm("mov.b64 {%0, %1}, %2;" : "=f"(r.x), "=f"(r.y) : "l"(v)); return r;
}

// ---------------- CSR build: ONE block, deterministic ----------------
__global__ void __launch_bounds__(1024) k_csr(const int* __restrict__ ei,
                                              const float* __restrict__ attr){
    __shared__ int sdeg[VV];
    __shared__ int scur[VV];
    int tid = threadIdx.x;
    for (int v = tid; v < VV; v += 1024) sdeg[v] = 0;
    __syncthreads();
    for (int e = tid; e < EE; e += 1024) atomicAdd(&sdeg[ei[EE+e]], 1);
    __syncthreads();
    if (tid == 0){
        int acc = 0;
        g_rowptr[0] = 0;
        for (int v = 0; v < VV; v++){ scur[v] = acc; acc += sdeg[v]; g_rowptr[v+1] = acc; }
    }
    __syncthreads();
    for (int e = tid; e < EE; e += 1024){
        int pos = atomicAdd(&scur[ei[EE+e]], 1);
        g_eid[pos] = e;
    }
    __syncthreads();
    for (int v = tid; v < VV; v += 1024){
        int s = g_rowptr[v], e = g_rowptr[v+1];
        for (int i = s+1; i < e; i++){
            int key = g_eid[i]; int k = i-1;
            while (k >= s && g_eid[k] > key){ g_eid[k+1] = g_eid[k]; k--; }
            g_eid[k+1] = key;
        }
        for (int i = s; i < e; i++){
            int id = g_eid[i];
            g_cols[i] = ei[id];
            g_vals[i] = attr[id];
        }
    }
}

// ---------------- weight folding: Wc = W_g @ Wi ----------------
__global__ void k_fold(const float* __restrict__ Wgd, const float* __restrict__ Wid,
                       const float* __restrict__ Wgc, const float* __restrict__ Wic){
    int i = blockIdx.x;
    int j = threadIdx.x;
    const float* Wg = (blockIdx.y == 0) ? Wgd : Wgc;
    const float* Wi = (blockIdx.y == 0) ? Wid : Wic;
    float*       Wc = (blockIdx.y == 0) ? g_Wcd : g_Wcc;
    float acc = 0.f;
    #pragma unroll
    for (int k = 0; k < LL; k++) acc += Wg[i*LL + k] * Wi[k*L3 + j];
    Wc[i*L3 + j] = acc;
}

// ---------------- encoder ----------------
__global__ void k_encode(const float* __restrict__ x, const float* __restrict__ W,
                         const float* __restrict__ b){
    __shared__ float xs[CC*32];
    __shared__ float Ws[CC*LL];
    __shared__ float bs[LL];
    int blk = blockIdx.x;
    int nv = blk / 5;
    int t0 = (blk % 5) * 32;
    int tid = threadIdx.x;
    for (int i = tid; i < CC*32; i += 256){
        int c = i / 32, tl = i % 32, t = t0 + tl;
        xs[c*32 + tl] = (t < TT) ? x[((size_t)nv*CC + c)*TT + t] : 0.f;
    }
    for (int i = tid; i < CC*LL; i += 256) Ws[i] = W[i];
    if (tid < LL) bs[tid] = b[tid];
    __syncthreads();
    int l = tid & 63, tg = tid >> 6;
    for (int tl = tg; tl < 32; tl += 4){
        int t = t0 + tl;
        if (t >= TT) break;
        float acc = bs[l];
        #pragma unroll
        for (int c = 0; c < CC; c++) acc += xs[c*32 + tl] * Ws[c*LL + l];
        g_xe[((size_t)t*NV + nv)*LL + l] = acc;
    }
}

// ---------------- gather only: agg = S.xe for all t ----------------
__global__ void __launch_bounds__(256) k_agg(){
    int b = blockIdx.x;
    int t   = b >> 7;
    int rem = b & 127;
    int n   = rem >> 4;
    int v0  = (rem & 15) * 128;
    int tid = threadIdx.x;
    const float* xb = g_xe  + ((size_t)t*NV + (size_t)n*VV) * LL;
    float*       ob = g_agg + ((size_t)t*NV + (size_t)n*VV + v0) * LL;
    int lane = tid & 63, rg = tid >> 6;
    for (int r = rg; r < 128; r += 4){
        int v = v0 + r;
        int s = g_rowptr[v], e = g_rowptr[v+1];
        float acc = 0.f;
        for (int idx = s; idx < e; idx++)
            acc += xb[(size_t)g_cols[idx]*LL + lane] * g_vals[idx];
        ob[(size_t)r*LL + lane] = acc;
    }
}

// ---------------- fused persistent domain scan: gi-GEMM + GRU, 150 steps -------------
// grid 128 (128 rows/block), 512 threads, dyn smem 164608 (1 block/SM, single wave)
__global__ void __launch_bounds__(512) k_domscan(const float* __restrict__ Wh,
                                                 const float* __restrict__ bias){
    extern __shared__ float sm[];
    float* Wst = sm;                 // [128][192]: rows0-63 = Wh, rows64-127 = Wcd
    float* hs  = Wst + 128*L3;       // [128][64]
    float* ags = hs + 128*LL;        // [128][64]
    float* bs  = ags + 128*LL;       // [192]
    int tid = threadIdx.x;
    int row0 = blockIdx.x * 128;
    for (int i = tid; i < (64*L3)/4; i += 512){
        ((float4*)Wst)[i]           = ((const float4*)Wh)[i];
        ((float4*)(Wst + 64*L3))[i] = ((const float4*)g_Wcd)[i];
    }
    for (int i = tid; i < 128*LL; i += 512) hs[i] = 0.f;
    if (tid < L3) bs[tid] = bias[tid];
    __syncthreads();

    int r0 = (tid >> 4) * 4, c0 = (tid & 15) * 4;

    for (int t = 0; t < TT; t++){
        // stream agg tile (sequential DRAM)
        const float4* src = (const float4*)(g_agg + ((size_t)t*NV + row0)*LL);
        for (int i = tid; i < (128*LL)/4; i += 512) ((float4*)ags)[i] = src[i];
        __syncthreads();

        u64 az[4][2], ar[4][2], anh[4][2], ang[4][2];
        {
            const u64* bz = (const u64*)(bs + c0);
            const u64* br = (const u64*)(bs + 64 + c0);
            const u64* bn = (const u64*)(bs + 128 + c0);
            u64 z0=bz[0], z1=bz[1], q0=br[0], q1=br[1], n0=bn[0], n1=bn[1];
            #pragma unroll
            for (int i=0;i<4;i++){ az[i][0]=z0; az[i][1]=z1; ar[i][0]=q0; ar[i][1]=q1;
                                   ang[i][0]=n0; ang[i][1]=n1; anh[i][0]=0ull; anh[i][1]=0ull; }
        }
        // part 1: h @ Wh (W rows 0..63); n-gate -> anh
        #pragma unroll 2
        for (int k0 = 0; k0 < 64; k0 += 4){
            float4 a[4];
            #pragma unroll
            for (int i=0;i<4;i++) a[i] = *(const float4*)(hs + (r0+i)*LL + k0);
            #pragma unroll
            for (int kk=0; kk<4; kk++){
                const float* wrow = Wst + (k0+kk)*L3;
                const u64* wz = (const u64*)(wrow + c0);
                const u64* wr = (const u64*)(wrow + 64 + c0);
                const u64* wn = (const u64*)(wrow + 128 + c0);
                u64 wz0=wz[0],wz1=wz[1],wr0=wr[0],wr1=wr[1],wn0=wn[0],wn1=wn[1];
                #pragma unroll
                for (int i=0;i<4;i++){
                    float av = (kk==0)?a[i].x:(kk==1)?a[i].y:(kk==2)?a[i].z:a[i].w;
                    u64 ad = f2dup(av);
                    az [i][0]=f2fma(ad,wz0,az [i][0]); az [i][1]=f2fma(ad,wz1,az [i][1]);
                    ar [i][0]=f2fma(ad,wr0,ar [i][0]); ar [i][1]=f2fma(ad,wr1,ar [i][1]);
                    anh[i][0]=f2fma(ad,wn0,anh[i][0]); anh[i][1]=f2fma(ad,wn1,anh[i][1]);
                }
            }
        }
        // part 2: agg @ Wcd (W rows 64..127); n-gate -> ang
        #pragma unroll 2
        for (int k0 = 0; k0 < 64; k0 += 4){
            float4 a[4];
            #pragma unroll
            for (int i=0;i<4;i++) a[i] = *(const float4*)(ags + (r0+i)*LL + k0);
            #pragma unroll
            for (int kk=0; kk<4; kk++){
                const float* wrow = Wst + (64 + k0 + kk)*L3;
                const u64* wz = (const u64*)(wrow + c0);
                const u64* wr = (const u64*)(wrow + 64 + c0);
                const u64* wn = (const u64*)(wrow + 128 + c0);
                u64 wz0=wz[0],wz1=wz[1],wr0=wr[0],wr1=wr[1],wn0=wn[0],wn1=wn[1];
                #pragma unroll
                for (int i=0;i<4;i++){
                    float av = (kk==0)?a[i].x:(kk==1)?a[i].y:(kk==2)?a[i].z:a[i].w;
                    u64 ad = f2dup(av);
                    az [i][0]=f2fma(ad,wz0,az [i][0]); az [i][1]=f2fma(ad,wz1,az [i][1]);
                    ar [i][0]=f2fma(ad,wr0,ar [i][0]); ar [i][1]=f2fma(ad,wr1,ar [i][1]);
                    ang[i][0]=f2fma(ad,wn0,ang[i][0]); ang[i][1]=f2fma(ad,wn1,ang[i][1]);
                }
            }
        }
        __syncthreads();   // all reads of hs/ags complete before gate writes
        #pragma unroll
        for (int i=0;i<4;i++){
            int r = r0 + i;
            float2 vz0=f2unpk(az[i][0]),  vz1=f2unpk(az[i][1]);
            float2 vr0=f2unpk(ar[i][0]),  vr1=f2unpk(ar[i][1]);
            float2 vh0=f2unpk(anh[i][0]), vh1=f2unpk(anh[i][1]);
            float2 vg0=f2unpk(ang[i][0]), vg1=f2unpk(ang[i][1]);
            float zz[4]={vz0.x,vz0.y,vz1.x,vz1.y};
            float rv[4]={vr0.x,vr0.y,vr1.x,vr1.y};
            float nh[4]={vh0.x,vh0.y,vh1.x,vh1.y};
            float ng[4]={vg0.x,vg0.y,vg1.x,vg1.y};
            #pragma unroll
            for (int j=0;j<4;j++){
                float z  = sigmf_(zz[j]);
                float rg = sigmf_(rv[j]);
                float nn = tanhf(ng[j] + rg*nh[j]);
                float hp = hs[r*LL + c0 + j];
                hs[r*LL + c0 + j] = (1.f-z)*nn + z*hp;
            }
        }
        __syncthreads();
    }
    for (int i = tid; i < 128*LL; i += 512) g_hd[(size_t)row0*LL + i] = hs[i];
}

// ---------------- domain MLP + cz precompute ----------------
__global__ void k_dommlp(const float* __restrict__ Wd1, const float* __restrict__ bd1,
                         const float* __restrict__ Wd2, const float* __restrict__ bd2,
                         const float* __restrict__ odeW1, const float* __restrict__ odeb1){
    extern __shared__ float sm[];
    float* W1s = sm;
    float* W2s = W1s + 4096;
    float* Wzs = W2s + 4096;
    float* hds = Wzs + 4096;
    float* t1s = hds + 1024;
    float* zDs = t1s + 1024;
    float* b1s = zDs + 1024;
    float* b2s = b1s + 64;
    float* bos = b2s + 64;
    int tid = threadIdx.x;
    int row0 = blockIdx.x * 16;
    for (int i = tid; i < 4096; i += 256){ W1s[i] = Wd1[i]; W2s[i] = Wd2[i]; Wzs[i] = odeW1[4096 + i]; }
    for (int i = tid; i < 16*LL; i += 256) hds[i] = g_hd[(size_t)row0*LL + i];
    if (tid < 64){ b1s[tid] = bd1[tid]; b2s[tid] = bd2[tid]; bos[tid] = odeb1[tid]; }
    __syncthreads();
    int j = tid & 63, rg = tid >> 6;
    for (int r = rg; r < 16; r += 4){
        float acc = b1s[j];
        #pragma unroll
        for (int k = 0; k < LL; k++) acc += hds[r*LL + k] * W1s[k*LL + j];
        t1s[r*LL + j] = tanhf(acc);
    }
    __syncthreads();
    for (int r = rg; r < 16; r += 4){
        float acc = b2s[j];
        #pragma unroll
        for (int k = 0; k < LL; k++) acc += t1s[r*LL + k] * W2s[k*LL + j];
        zDs[r*LL + j] = acc;
    }
    __syncthreads();
    for (int r = rg; r < 16; r += 4){
        float acc = bos[j];
        #pragma unroll
        for (int k = 0; k < LL; k++) acc += zDs[r*LL + k] * Wzs[k*LL + j];
        g_cz[(size_t)(row0+r)*LL + j] = acc;
    }
}

// ---------------- fused persistent correction scan: ODE + gi-GEMM + GRU, 149 steps ----
// grid 128 (128 rows/block), 512 threads, dyn smem 230400 (1 block/SM, single wave)
__global__ void __launch_bounds__(512) k_corrscan(const float* __restrict__ odeW1,
        const float* __restrict__ odeW2, const float* __restrict__ odeb2,
        const float* __restrict__ Wh, const float* __restrict__ bias){
    extern __shared__ float sm[];
    float* Wst = sm;               // [128][192]: rows0-63 = Wh, rows64-127 = Wcc
    float* W1s = Wst + 128*L3;     // [64][64]
    float* W2s = W1s + 4096;       // [64][64]
    float* hs  = W2s + 4096;       // [128][64]
    float* hos = hs  + 128*LL;     // [128][64]
    float* Xs  = hos + 128*LL;     // [128][64]  t1 buffer, then agg tile (time-shared)
    float* bs  = Xs  + 128*LL;     // [192]
    float* b2s = bs + L3;          // [64]
    int tid = threadIdx.x;
    int row0 = blockIdx.x * 128;
    for (int i = tid; i < (64*L3)/4; i += 512){
        ((float4*)Wst)[i]           = ((const float4*)Wh)[i];
        ((float4*)(Wst + 64*L3))[i] = ((const float4*)g_Wcc)[i];
    }
    for (int i = tid; i < 1024; i += 512){ ((float4*)W1s)[i] = ((const float4*)odeW1)[i];
                                           ((float4*)W2s)[i] = ((const float4*)odeW2)[i]; }
    for (int i = tid; i < (128*LL)/4; i += 512)
        ((float4*)hs)[i] = ((const float4*)(g_xe + (size_t)row0*LL))[i];   // h0 = xe[0]
    if (tid < L3) bs[tid] = bias[tid];
    if (tid < 64) b2s[tid] = odeb2[tid];
    __syncthreads();

    int p_r0 = (tid >> 3) * 2, p_c0 = (tid & 7) * 8;    // phase1/2: 2 rows x 8 cols
    int g_r0 = (tid >> 4) * 4, g_c0 = (tid & 15) * 4;   // phase3:   4 rows x 4 cols/gate
    const float* czp = g_cz + (size_t)row0 * LL;

    for (int t = 1; t < TT; t++){
        // prefetch cz for this thread's phase1 tile (L2-resident; hidden under GEMM)
        float4 cz00 = __ldg((const float4*)(czp + (size_t)(p_r0+0)*LL + p_c0));
        float4 cz01 = __ldg((const float4*)(czp + (size_t)(p_r0+0)*LL + p_c0 + 4));
        float4 cz10 = __ldg((const float4*)(czp + (size_t)(p_r0+1)*LL + p_c0));
        float4 cz11 = __ldg((const float4*)(czp + (size_t)(p_r0+1)*LL + p_c0 + 4));

        // phase1: Xs(t1) = tanh(hs @ W1 + cz)
        {
            u64 acc[2][4];
            #pragma unroll
            for (int i=0;i<2;i++){ acc[i][0]=0ull; acc[i][1]=0ull; acc[i][2]=0ull; acc[i][3]=0ull; }
            #pragma unroll 4
            for (int k0 = 0; k0 < 64; k0 += 4){
                float4 a0 = *(const float4*)(hs + (p_r0+0)*LL + k0);
                float4 a1 = *(const float4*)(hs + (p_r0+1)*LL + k0);
                #pragma unroll
                for (int kk=0; kk<4; kk++){
                    const u64* wp = (const u64*)(W1s + (k0+kk)*LL + p_c0);
                    u64 w0=wp[0], w1=wp[1], w2=wp[2], w3=wp[3];
                    float v0 = (kk==0)?a0.x:(kk==1)?a0.y:(kk==2)?a0.z:a0.w;
                    float v1 = (kk==0)?a1.x:(kk==1)?a1.y:(kk==2)?a1.z:a1.w;
                    u64 d0 = f2dup(v0), d1 = f2dup(v1);
                    acc[0][0]=f2fma(d0,w0,acc[0][0]); acc[0][1]=f2fma(d0,w1,acc[0][1]);
                    acc[0][2]=f2fma(d0,w2,acc[0][2]); acc[0][3]=f2fma(d0,w3,acc[0][3]);
                    acc[1][0]=f2fma(d1,w0,acc[1][0]); acc[1][1]=f2fma(d1,w1,acc[1][1]);
                    acc[1][2]=f2fma(d1,w2,acc[1][2]); acc[1][3]=f2fma(d1,w3,acc[1][3]);
                }
            }
            float czf[2][8] = {{cz00.x,cz00.y,cz00.z,cz00.w, cz01.x,cz01.y,cz01.z,cz01.w},
                               {cz10.x,cz10.y,cz10.z,cz10.w, cz11.x,cz11.y,cz11.z,cz11.w}};
            #pragma unroll
            for (int i=0;i<2;i++)
                #pragma unroll
                for (int p=0;p<4;p++){
                    float2 v = f2unpk(acc[i][p]);
                    Xs[(p_r0+i)*LL + p_c0 + 2*p    ] = tanhf(v.x + czf[i][2*p  ]);
                    Xs[(p_r0+i)*LL + p_c0 + 2*p + 1] = tanhf(v.y + czf[i][2*p+1]);
                }
        }
        __syncthreads();
        // phase2: hos = hs + Xs @ W2 + b2
        {
            u64 acc[2][4];
            {
                const u64* bp = (const u64*)(b2s + p_c0);
                u64 b0=bp[0], b1=bp[1], b2v=bp[2], b3=bp[3];
                acc[0][0]=b0; acc[0][1]=b1; acc[0][2]=b2v; acc[0][3]=b3;
                acc[1][0]=b0; acc[1][1]=b1; acc[1][2]=b2v; acc[1][3]=b3;
            }
            #pragma unroll 4
            for (int k0 = 0; k0 < 64; k0 += 4){
                float4 a0 = *(const float4*)(Xs + (p_r0+0)*LL + k0);
                float4 a1 = *(const float4*)(Xs + (p_r0+1)*LL + k0);
                #pragma unroll
                for (int kk=0; kk<4; kk++){
                    const u64* wp = (const u64*)(W2s + (k0+kk)*LL + p_c0);
                    u64 w0=wp[0], w1=wp[1], w2=wp[2], w3=wp[3];
                    float v0 = (kk==0)?a0.x:(kk==1)?a0.y:(kk==2)?a0.z:a0.w;
                    float v1 = (kk==0)?a1.x:(kk==1)?a1.y:(kk==2)?a1.z:a1.w;
                    u64 d0 = f2dup(v0), d1 = f2dup(v1);
                    acc[0][0]=f2fma(d0,w0,acc[0][0]); acc[0][1]=f2fma(d0,w1,acc[0][1]);
                    acc[0][2]=f2fma(d0,w2,acc[0][2]); acc[0][3]=f2fma(d0,w3,acc[0][3]);
                    acc[1][0]=f2fma(d1,w0,acc[1][0]); acc[1][1]=f2fma(d1,w1,acc[1][1]);
                    acc[1][2]=f2fma(d1,w2,acc[1][2]); acc[1][3]=f2fma(d1,w3,acc[1][3]);
                }
            }
            #pragma unroll
            for (int i=0;i<2;i++)
                #pragma unroll
                for (int p=0;p<4;p++){
                    float2 v = f2unpk(acc[i][p]);
                    int base = (p_r0+i)*LL + p_c0 + 2*p;
                    hos[base    ] = hs[base    ] + v.x;
                    hos[base + 1] = hs[base + 1] + v.y;
                }
        }
        __syncthreads();
        // copy agg[t] into Xs (t1 dead)
        {
            const float4* asrc = (const float4*)(g_agg + ((size_t)t*NV + row0)*LL);
            for (int i = tid; i < (128*LL)/4; i += 512) ((float4*)Xs)[i] = asrc[i];
        }
        __syncthreads();
        // phase3: GRU stacked-K GEMM: A = [hos | agg], n-gate split
        u64 az[4][2], ar[4][2], anh[4][2], ang[4][2];
        {
            const u64* bz = (const u64*)(bs + g_c0);
            const u64* br = (const u64*)(bs + 64 + g_c0);
            const u64* bn = (const u64*)(bs + 128 + g_c0);
            u64 z0=bz[0], z1=bz[1], q0=br[0], q1=br[1], n0=bn[0], n1=bn[1];
            #pragma unroll
            for (int i=0;i<4;i++){ az[i][0]=z0; az[i][1]=z1; ar[i][0]=q0; ar[i][1]=q1;
                                   ang[i][0]=n0; ang[i][1]=n1; anh[i][0]=0ull; anh[i][1]=0ull; }
        }
        #pragma unroll 2
        for (int k0 = 0; k0 < 64; k0 += 4){
            float4 a[4];
            #pragma unroll
            for (int i=0;i<4;i++) a[i] = *(const float4*)(hos + (g_r0+i)*LL + k0);
            #pragma unroll
            for (int kk=0; kk<4; kk++){
                const float* wrow = Wst + (k0+kk)*L3;
                const u64* wz = (const u64*)(wrow + g_c0);
                const u64* wr = (const u64*)(wrow + 64 + g_c0);
                const u64* wn = (const u64*)(wrow + 128 + g_c0);
                u64 wz0=wz[0],wz1=wz[1],wr0=wr[0],wr1=wr[1],wn0=wn[0],wn1=wn[1];
                #pragma unroll
                for (int i=0;i<4;i++){
                    float av = (kk==0)?a[i].x:(kk==1)?a[i].y:(kk==2)?a[i].z:a[i].w;
                    u64 ad = f2dup(av);
                    az [i][0]=f2fma(ad,wz0,az [i][0]); az [i][1]=f2fma(ad,wz1,az [i][1]);
                    ar [i][0]=f2fma(ad,wr0,ar [i][0]); ar [i][1]=f2fma(ad,wr1,ar [i][1]);
                    anh[i][0]=f2fma(ad,wn0,anh[i][0]); anh[i][1]=f2fma(ad,wn1,anh[i][1]);
                }
            }
        }
        #pragma unroll 2
        for (int k0 = 0; k0 < 64; k0 += 4){
            float4 a[4];
            #pragma unroll
            for (int i=0;i<4;i++) a[i] = *(const float4*)(Xs + (g_r0+i)*LL + k0);
            #pragma unroll
            for (int kk=0; kk<4; kk++){
                const float* wrow = Wst + (64 + k0 + kk)*L3;
                const u64* wz = (const u64*)(wrow + g_c0);
                const u64* wr = (const u64*)(wrow + 64 + g_c0);
                const u64* wn = (const u64*)(wrow + 128 + g_c0);
                u64 wz0=wz[0],wz1=wz[1],wr0=wr[0],wr1=wr[1],wn0=wn[0],wn1=wn[1];
                #pragma unroll
                for (int i=0;i<4;i++){
                    float av = (kk==0)?a[i].x:(kk==1)?a[i].y:(kk==2)?a[i].z:a[i].w;
                    u64 ad = f2dup(av);
                    az [i][0]=f2fma(ad,wz0,az [i][0]); az [i][1]=f2fma(ad,wz1,az [i][1]);
                    ar [i][0]=f2fma(ad,wr0,ar [i][0]); ar [i][1]=f2fma(ad,wr1,ar [i][1]);
                    ang[i][0]=f2fma(ad,wn0,ang[i][0]); ang[i][1]=f2fma(ad,wn1,ang[i][1]);
                }
            }
        }
        __syncthreads();   // all reads of hos/Xs/hs done before hs writes
        #pragma unroll
        for (int i=0;i<4;i++){
            int r = g_r0 + i;
            float2 vz0=f2unpk(az[i][0]),  vz1=f2unpk(az[i][1]);
            float2 vr0=f2unpk(ar[i][0]),  vr1=f2unpk(ar[i][1]);
            float2 vh0=f2unpk(anh[i][0]), vh1=f2unpk(anh[i][1]);
            float2 vg0=f2unpk(ang[i][0]), vg1=f2unpk(ang[i][1]);
            float zz[4]={vz0.x,vz0.y,vz1.x,vz1.y};
            float rv[4]={vr0.x,vr0.y,vr1.x,vr1.y};
            float nh[4]={vh0.x,vh0.y,vh1.x,vh1.y};
            float ng[4]={vg0.x,vg0.y,vg1.x,vg1.y};
            float hn4[4];
            #pragma unroll
            for (int j=0;j<4;j++){
                float z  = sigmf_(zz[j]);
                float rg = sigmf_(rv[j]);
                float nn = tanhf(ng[j] + rg*nh[j]);
                float ho = hos[r*LL + g_c0 + j];
                hn4[j] = (1.f-z)*nn + z*ho;
            }
            #pragma unroll
            for (int j=0;j<4;j++) hs[r*LL + g_c0 + j] = hn4[j];
            *(float4*)(g_xe + ((size_t)t*NV + row0 + r)*LL + g_c0)
                = make_float4(hn4[0], hn4[1], hn4[2], hn4[3]);
        }
        __syncthreads();   // hs writes visible before next phase1
    }
}

// ---------------- decoder ----------------
__global__ void k_decode(float* __restrict__ out, const float* __restrict__ W,
                         const float* __restrict__ b){
    __shared__ float zs[32*65];
    __shared__ float Ws[LL*CC];
    __shared__ float bs[CC];
    int blk = blockIdx.x;
    int nv = blk / 5;
    int t0 = (blk % 5) * 32;
    int tid = threadIdx.x;
    for (int i = tid; i < 32*LL; i += 256){
        int tl = i >> 6, l = i & 63, t = t0 + tl;
        zs[tl*65 + l] = (t < TT) ? g_xe[((size_t)t*NV + nv)*LL + l] : 0.f;
    }
    for (int i = tid; i < LL*CC; i += 256) Ws[i] = W[i];
    if (tid < CC) bs[tid] = b[tid];
    __syncthreads();
    for (int o = tid; o < 512; o += 256){
        int c = o >> 5, tl = o & 31, t = t0 + tl;
        if (t >= TT) continue;
        float acc = bs[c];
        #pragma unroll
        for (int l = 0; l < LL; l++) acc += zs[tl*65 + l] * Ws[l*CC + c];
        out[((size_t)nv*CC + c)*TT + t] = acc;
    }
}

// ---------------- launch ----------------
extern "C" void kernel_launch(void* const* d_in, const int* in_sizes, int n_in,
                              void* d_out, int out_size){
    const float* x      = (const float*)d_in[0];
    const int*   ei     = (const int*)  d_in[1];
    const float* attr   = (const float*)d_in[2];
    const float* W_enc  = (const float*)d_in[3];
    const float* b_enc  = (const float*)d_in[4];
    const float* W_gd   = (const float*)d_in[5];
    const float* gd_Wi  = (const float*)d_in[6];
    const float* gd_Wh  = (const float*)d_in[7];
    const float* gd_b   = (const float*)d_in[8];
    const float* W_dom1 = (const float*)d_in[9];
    const float* b_dom1 = (const float*)d_in[10];
    const float* W_dom2 = (const float*)d_in[11];
    const float* b_dom2 = (const float*)d_in[12];
    const float* ode_W1 = (const float*)d_in[13];
    const float* ode_b1 = (const float*)d_in[14];
    const float* ode_W2 = (const float*)d_in[15];
    const float* ode_b2 = (const float*)d_in[16];
    const float* W_gc   = (const float*)d_in[17];
    const float* gc_Wi  = (const float*)d_in[18];
    const float* gc_Wh  = (const float*)d_in[19];
    const float* gc_b   = (const float*)d_in[20];
    const float* W_dec  = (const float*)d_in[21];
    const float* b_dec  = (const float*)d_in[22];
    float* out = (float*)d_out;

    const int SM_DOMS  = (128*L3 + 2*128*LL + L3) * 4;                         // 164608
    const int SM_CORRS = (128*L3 + 4096 + 4096 + 3*128*LL + L3 + 64) * 4;      // 230400
    const int SM_MLP   = (3*4096 + 3*1024 + 3*64) * 4;                         // 62208

    cudaFuncSetAttribute(k_domscan,  cudaFuncAttributeMaxDynamicSharedMemorySize, SM_DOMS);
    cudaFuncSetAttribute(k_corrscan, cudaFuncAttributeMaxDynamicSharedMemorySize, SM_CORRS);
    cudaFuncSetAttribute(k_dommlp,   cudaFuncAttributeMaxDynamicSharedMemorySize, SM_MLP);

    // 1: weight folding
    k_fold<<<dim3(64, 2), L3>>>(W_gd, gd_Wi, W_gc, gc_Wi);
    // 2: encoder
    k_encode<<<NV*5, 256>>>(x, W_enc, b_enc);
    // 3: CSR build (one block, deterministic)
    k_csr <<<1, 1024>>>(ei, attr);
    // 4: gather ONCE (pass-independent)
    k_agg <<<TT*128, 256>>>();
    // 5: fused persistent domain scan (gi-GEMM + GRU)
    k_domscan<<<NV/128, 512, SM_DOMS>>>(gd_Wh, gd_b);
    // 6: domain MLP + cz
    k_dommlp<<<NV/16, 256, SM_MLP>>>(W_dom1, b_dom1, W_dom2, b_dom2, ode_W1, ode_b1);
    // 7: fused persistent correction scan (ODE + gi-GEMM + GRU)
    k_corrscan<<<NV/128, 512, SM_CORRS>>>(ode_W1, ode_W2, ode_b2, gc_Wh, gc_b);
    // 8: decoder
    k_decode<<<NV*5, 256>>>(out, W_dec, b_dec);
}

// round 14
// speedup vs baseline: 2.1230x; 1.0714x over previous
#include <cuda_runtime.h>
#include <math.h>

#define TT 150
#define NB 8
#define VV 2048
#define CC 16
#define LL 64
#define L3 192
#define EE 32768
#define NV (NB*VV)   // 16384

typedef unsigned long long u64;

// ---------------- static device scratch (~1.3 GB .bss) ----------------
__device__ float g_xe [(size_t)TT*NV*LL];   // encoder output; later overwritten with z
__device__ float g_agg[(size_t)TT*NV*LL];   // gathered S.xe (pass-independent)
__device__ float g_hd [NV*LL];              // domain hidden (final)
__device__ float g_cz [NV*LL];              // z_D @ ode_W1[64:128] + ode_b1
__device__ float g_Wcd[LL*L3];              // W_gd @ gd_Wi
__device__ float g_Wcc[LL*L3];              // W_gc @ gc_Wi
__device__ int   g_rowptr[VV+1];
__device__ int   g_eid [EE];
__device__ int   g_cols[EE];
__device__ float g_vals[EE];

// fast gates: __expf + fast divide (abs err ~1e-6; threshold 1e-3)
__device__ __forceinline__ float fsigm(float x){
    return __fdividef(1.f, 1.f + __expf(-x));
}
__device__ __forceinline__ float ftanh(float x){
    float xc = fminf(12.f, fmaxf(-12.f, x));
    float e = __expf(2.f*xc);
    return __fdividef(e - 1.f, e + 1.f);
}

// packed fp32x2 FMA (Blackwell FFMA2 — 2x fp32 FMA throughput, bitwise == scalar)
__device__ __forceinline__ u64 f2fma(u64 a, u64 b, u64 c){
    u64 d; asm("fma.rn.f32x2 %0, %1, %2, %3;" : "=l"(d) : "l"(a), "l"(b), "l"(c)); return d;
}
__device__ __forceinline__ u64 f2dup(float x){
    u64 d; asm("mov.b64 %0, {%1, %2};" : "=l"(d) : "f"(x), "f"(x)); return d;
}
__device__ __forceinline__ float2 f2unpk(u64 v){
    float2 r; asm("mov.b64 {%0, %1}, %2;" : "=f"(r.x), "=f"(r.y) : "l"(v)); return r;
}

// ---------------- CSR build + weight folding: ONE block, deterministic ----------------
__global__ void __launch_bounds__(1024) k_csrfold(const int* __restrict__ ei,
        const float* __restrict__ attr,
        const float* __restrict__ Wgd, const float* __restrict__ Wid,
        const float* __restrict__ Wgc, const float* __restrict__ Wic){
    __shared__ int sdeg[VV];
    __shared__ int scur[VV];
    int tid = threadIdx.x;
    // fold: Wc = W_g @ Wi  ([64,64]@[64,192]) for both pipelines
    for (int o = tid; o < LL*L3; o += 1024){
        int i = o / L3, j = o % L3;
        float a0 = 0.f, a1 = 0.f;
        #pragma unroll
        for (int k = 0; k < LL; k++){
            a0 += Wgd[i*LL + k] * Wid[k*L3 + j];
            a1 += Wgc[i*LL + k] * Wic[k*L3 + j];
        }
        g_Wcd[o] = a0;
        g_Wcc[o] = a1;
    }
    // CSR by dst, rows sorted by edge id (deterministic summation order)
    for (int v = tid; v < VV; v += 1024) sdeg[v] = 0;
    __syncthreads();
    for (int e = tid; e < EE; e += 1024) atomicAdd(&sdeg[ei[EE+e]], 1);
    __syncthreads();
    if (tid == 0){
        int acc = 0;
        g_rowptr[0] = 0;
        for (int v = 0; v < VV; v++){ scur[v] = acc; acc += sdeg[v]; g_rowptr[v+1] = acc; }
    }
    __syncthreads();
    for (int e = tid; e < EE; e += 1024){
        int pos = atomicAdd(&scur[ei[EE+e]], 1);
        g_eid[pos] = e;
    }
    __syncthreads();
    for (int v = tid; v < VV; v += 1024){
        int s = g_rowptr[v], e = g_rowptr[v+1];
        for (int i = s+1; i < e; i++){
            int key = g_eid[i]; int k = i-1;
            while (k >= s && g_eid[k] > key){ g_eid[k+1] = g_eid[k]; k--; }
            g_eid[k+1] = key;
        }
        for (int i = s; i < e; i++){
            int id = g_eid[i];
            g_cols[i] = ei[id];
            g_vals[i] = attr[id];
        }
    }
}

// ---------------- encoder ----------------
__global__ void k_encode(const float* __restrict__ x, const float* __restrict__ W,
                         const float* __restrict__ b){
    __shared__ float xs[CC*32];
    __shared__ float Ws[CC*LL];
    __shared__ float bs[LL];
    int blk = blockIdx.x;
    int nv = blk / 5;
    int t0 = (blk % 5) * 32;
    int tid = threadIdx.x;
    for (int i = tid; i < CC*32; i += 256){
        int c = i / 32, tl = i % 32, t = t0 + tl;
        xs[c*32 + tl] = (t < TT) ? x[((size_t)nv*CC + c)*TT + t] : 0.f;
    }
    for (int i = tid; i < CC*LL; i += 256) Ws[i] = W[i];
    if (tid < LL) bs[tid] = b[tid];
    __syncthreads();
    int l = tid & 63, tg = tid >> 6;
    for (int tl = tg; tl < 32; tl += 4){
        int t = t0 + tl;
        if (t >= TT) break;
        float acc = bs[l];
        #pragma unroll
        for (int c = 0; c < CC; c++) acc += xs[c*32 + tl] * Ws[c*LL + l];
        g_xe[((size_t)t*NV + nv)*LL + l] = acc;
    }
}

// ---------------- gather only: agg = S.xe for all t ----------------
__global__ void __launch_bounds__(256) k_agg(){
    int b = blockIdx.x;
    int t   = b >> 7;
    int rem = b & 127;
    int n   = rem >> 4;
    int v0  = (rem & 15) * 128;
    int tid = threadIdx.x;
    const float* xb = g_xe  + ((size_t)t*NV + (size_t)n*VV) * LL;
    float*       ob = g_agg + ((size_t)t*NV + (size_t)n*VV + v0) * LL;
    int lane = tid & 63, rg = tid >> 6;
    for (int r = rg; r < 128; r += 4){
        int v = v0 + r;
        int s = g_rowptr[v], e = g_rowptr[v+1];
        float acc = 0.f;
        for (int idx = s; idx < e; idx++)
            acc += xb[(size_t)g_cols[idx]*LL + lane] * g_vals[idx];
        ob[(size_t)r*LL + lane] = acc;
    }
}

// ---------------- fused persistent domain scan: gi-GEMM + GRU, 150 steps -------------
// grid 128 (128 rows/block), 512 threads, dyn smem 164608 (1 block/SM, single wave)
__global__ void __launch_bounds__(512) k_domscan(const float* __restrict__ Wh,
                                                 const float* __restrict__ bias){
    extern __shared__ float sm[];
    float* Wst = sm;                 // [128][192]: rows0-63 = Wh, rows64-127 = Wcd
    float* hs  = Wst + 128*L3;       // [128][64]
    float* ags = hs + 128*LL;        // [128][64]
    float* bs  = ags + 128*LL;       // [192]
    int tid = threadIdx.x;
    int row0 = blockIdx.x * 128;
    for (int i = tid; i < (64*L3)/4; i += 512){
        ((float4*)Wst)[i]           = ((const float4*)Wh)[i];
        ((float4*)(Wst + 64*L3))[i] = ((const float4*)g_Wcd)[i];
    }
    for (int i = tid; i < 128*LL; i += 512) hs[i] = 0.f;
    if (tid < L3) bs[tid] = bias[tid];
    // preload agg tile for t=0
    {
        const float4* src = (const float4*)(g_agg + (size_t)row0*LL);
        #pragma unroll
        for (int j = 0; j < 4; j++) ((float4*)ags)[tid + j*512] = src[tid + j*512];
    }
    __syncthreads();

    int r0 = (tid >> 4) * 4, c0 = (tid & 15) * 4;

    for (int t = 0; t < TT; t++){
        // prefetch next agg tile into registers (hidden under this step's GEMM)
        float4 pf[4];
        if (t + 1 < TT){
            const float4* src = (const float4*)(g_agg + ((size_t)(t+1)*NV + row0)*LL);
            #pragma unroll
            for (int j = 0; j < 4; j++) pf[j] = src[tid + j*512];
        }

        u64 az[4][2], ar[4][2], anh[4][2], ang[4][2];
        {
            const u64* bz = (const u64*)(bs + c0);
            const u64* br = (const u64*)(bs + 64 + c0);
            const u64* bn = (const u64*)(bs + 128 + c0);
            u64 z0=bz[0], z1=bz[1], q0=br[0], q1=br[1], n0=bn[0], n1=bn[1];
            #pragma unroll
            for (int i=0;i<4;i++){ az[i][0]=z0; az[i][1]=z1; ar[i][0]=q0; ar[i][1]=q1;
                                   ang[i][0]=n0; ang[i][1]=n1; anh[i][0]=0ull; anh[i][1]=0ull; }
        }
        // part 1: h @ Wh (W rows 0..63); n-gate -> anh
        #pragma unroll 2
        for (int k0 = 0; k0 < 64; k0 += 4){
            float4 a[4];
            #pragma unroll
            for (int i=0;i<4;i++) a[i] = *(const float4*)(hs + (r0+i)*LL + k0);
            #pragma unroll
            for (int kk=0; kk<4; kk++){
                const float* wrow = Wst + (k0+kk)*L3;
                const u64* wz = (const u64*)(wrow + c0);
                const u64* wr = (const u64*)(wrow + 64 + c0);
                const u64* wn = (const u64*)(wrow + 128 + c0);
                u64 wz0=wz[0],wz1=wz[1],wr0=wr[0],wr1=wr[1],wn0=wn[0],wn1=wn[1];
                #pragma unroll
                for (int i=0;i<4;i++){
                    float av = (kk==0)?a[i].x:(kk==1)?a[i].y:(kk==2)?a[i].z:a[i].w;
                    u64 ad = f2dup(av);
                    az [i][0]=f2fma(ad,wz0,az [i][0]); az [i][1]=f2fma(ad,wz1,az [i][1]);
                    ar [i][0]=f2fma(ad,wr0,ar [i][0]); ar [i][1]=f2fma(ad,wr1,ar [i][1]);
                    anh[i][0]=f2fma(ad,wn0,anh[i][0]); anh[i][1]=f2fma(ad,wn1,anh[i][1]);
                }
            }
        }
        // part 2: agg @ Wcd (W rows 64..127); n-gate -> ang
        #pragma unroll 2
        for (int k0 = 0; k0 < 64; k0 += 4){
            float4 a[4];
            #pragma unroll
            for (int i=0;i<4;i++) a[i] = *(const float4*)(ags + (r0+i)*LL + k0);
            #pragma unroll
            for (int kk=0; kk<4; kk++){
                const float* wrow = Wst + (64 + k0 + kk)*L3;
                const u64* wz = (const u64*)(wrow + c0);
                const u64* wr = (const u64*)(wrow + 64 + c0);
                const u64* wn = (const u64*)(wrow + 128 + c0);
                u64 wz0=wz[0],wz1=wz[1],wr0=wr[0],wr1=wr[1],wn0=wn[0],wn1=wn[1];
                #pragma unroll
                for (int i=0;i<4;i++){
                    float av = (kk==0)?a[i].x:(kk==1)?a[i].y:(kk==2)?a[i].z:a[i].w;
                    u64 ad = f2dup(av);
                    az [i][0]=f2fma(ad,wz0,az [i][0]); az [i][1]=f2fma(ad,wz1,az [i][1]);
                    ar [i][0]=f2fma(ad,wr0,ar [i][0]); ar [i][1]=f2fma(ad,wr1,ar [i][1]);
                    ang[i][0]=f2fma(ad,wn0,ang[i][0]); ang[i][1]=f2fma(ad,wn1,ang[i][1]);
                }
            }
        }
        __syncthreads();   // all reads of hs/ags complete before hs writes / ags overwrite
        // store prefetched next tile into ags (readers done)
        if (t + 1 < TT){
            #pragma unroll
            for (int j = 0; j < 4; j++) ((float4*)ags)[tid + j*512] = pf[j];
        }
        #pragma unroll
        for (int i=0;i<4;i++){
            int r = r0 + i;
            float2 vz0=f2unpk(az[i][0]),  vz1=f2unpk(az[i][1]);
            float2 vr0=f2unpk(ar[i][0]),  vr1=f2unpk(ar[i][1]);
            float2 vh0=f2unpk(anh[i][0]), vh1=f2unpk(anh[i][1]);
            float2 vg0=f2unpk(ang[i][0]), vg1=f2unpk(ang[i][1]);
            float zz[4]={vz0.x,vz0.y,vz1.x,vz1.y};
            float rv[4]={vr0.x,vr0.y,vr1.x,vr1.y};
            float nh[4]={vh0.x,vh0.y,vh1.x,vh1.y};
            float ng[4]={vg0.x,vg0.y,vg1.x,vg1.y};
            #pragma unroll
            for (int j=0;j<4;j++){
                float z  = fsigm(zz[j]);
                float rg = fsigm(rv[j]);
                float nn = ftanh(ng[j] + rg*nh[j]);
                float hp = hs[r*LL + c0 + j];
                hs[r*LL + c0 + j] = (1.f-z)*nn + z*hp;
            }
        }
        __syncthreads();
    }
    for (int i = tid; i < 128*LL; i += 512) g_hd[(size_t)row0*LL + i] = hs[i];
}

// ---------------- domain MLP + cz precompute ----------------
__global__ void k_dommlp(const float* __restrict__ Wd1, const float* __restrict__ bd1,
                         const float* __restrict__ Wd2, const float* __restrict__ bd2,
                         const float* __restrict__ odeW1, const float* __restrict__ odeb1){
    extern __shared__ float sm[];
    float* W1s = sm;
    float* W2s = W1s + 4096;
    float* Wzs = W2s + 4096;
    float* hds = Wzs + 4096;
    float* t1s = hds + 1024;
    float* zDs = t1s + 1024;
    float* b1s = zDs + 1024;
    float* b2s = b1s + 64;
    float* bos = b2s + 64;
    int tid = threadIdx.x;
    int row0 = blockIdx.x * 16;
    for (int i = tid; i < 4096; i += 256){ W1s[i] = Wd1[i]; W2s[i] = Wd2[i]; Wzs[i] = odeW1[4096 + i]; }
    for (int i = tid; i < 16*LL; i += 256) hds[i] = g_hd[(size_t)row0*LL + i];
    if (tid < 64){ b1s[tid] = bd1[tid]; b2s[tid] = bd2[tid]; bos[tid] = odeb1[tid]; }
    __syncthreads();
    int j = tid & 63, rg = tid >> 6;
    for (int r = rg; r < 16; r += 4){
        float acc = b1s[j];
        #pragma unroll
        for (int k = 0; k < LL; k++) acc += hds[r*LL + k] * W1s[k*LL + j];
        t1s[r*LL + j] = ftanh(acc);
    }
    __syncthreads();
    for (int r = rg; r < 16; r += 4){
        float acc = b2s[j];
        #pragma unroll
        for (int k = 0; k < LL; k++) acc += t1s[r*LL + k] * W2s[k*LL + j];
        zDs[r*LL + j] = acc;
    }
    __syncthreads();
    for (int r = rg; r < 16; r += 4){
        float acc = bos[j];
        #pragma unroll
        for (int k = 0; k < LL; k++) acc += zDs[r*LL + k] * Wzs[k*LL + j];
        g_cz[(size_t)(row0+r)*LL + j] = acc;
    }
}

// ---------------- fused persistent correction scan: ODE + gi-GEMM + GRU, 149 steps ----
// grid 128 (128 rows/block), 512 threads, dyn smem 230400 (1 block/SM, single wave)
__global__ void __launch_bounds__(512) k_corrscan(const float* __restrict__ odeW1,
        const float* __restrict__ odeW2, const float* __restrict__ odeb2,
        const float* __restrict__ Wh, const float* __restrict__ bias){
    extern __shared__ float sm[];
    float* Wst = sm;               // [128][192]: rows0-63 = Wh, rows64-127 = Wcc
    float* W1s = Wst + 128*L3;     // [64][64]
    float* W2s = W1s + 4096;       // [64][64]
    float* hs  = W2s + 4096;       // [128][64]
    float* hos = hs  + 128*LL;     // [128][64]
    float* Xs  = hos + 128*LL;     // [128][64]  t1 buffer, then agg tile (time-shared)
    float* bs  = Xs  + 128*LL;     // [192]
    float* b2s = bs + L3;          // [64]
    int tid = threadIdx.x;
    int row0 = blockIdx.x * 128;
    for (int i = tid; i < (64*L3)/4; i += 512){
        ((float4*)Wst)[i]           = ((const float4*)Wh)[i];
        ((float4*)(Wst + 64*L3))[i] = ((const float4*)g_Wcc)[i];
    }
    for (int i = tid; i < 1024; i += 512){ ((float4*)W1s)[i] = ((const float4*)odeW1)[i];
                                           ((float4*)W2s)[i] = ((const float4*)odeW2)[i]; }
    for (int i = tid; i < (128*LL)/4; i += 512)
        ((float4*)hs)[i] = ((const float4*)(g_xe + (size_t)row0*LL))[i];   // h0 = xe[0]
    if (tid < L3) bs[tid] = bias[tid];
    if (tid < 64) b2s[tid] = odeb2[tid];
    __syncthreads();

    int p_r0 = (tid >> 3) * 2, p_c0 = (tid & 7) * 8;    // phase1/2: 2 rows x 8 cols
    int g_r0 = (tid >> 4) * 4, g_c0 = (tid & 15) * 4;   // phase3:   4 rows x 4 cols/gate
    const float* czp = g_cz + (size_t)row0 * LL;

    // cz is loop-invariant: load ONCE into registers
    float4 cz00 = __ldg((const float4*)(czp + (size_t)(p_r0+0)*LL + p_c0));
    float4 cz01 = __ldg((const float4*)(czp + (size_t)(p_r0+0)*LL + p_c0 + 4));
    float4 cz10 = __ldg((const float4*)(czp + (size_t)(p_r0+1)*LL + p_c0));
    float4 cz11 = __ldg((const float4*)(czp + (size_t)(p_r0+1)*LL + p_c0 + 4));
    float czf[2][8] = {{cz00.x,cz00.y,cz00.z,cz00.w, cz01.x,cz01.y,cz01.z,cz01.w},
                       {cz10.x,cz10.y,cz10.z,cz10.w, cz11.x,cz11.y,cz11.z,cz11.w}};

    for (int t = 1; t < TT; t++){
        // prefetch this step's agg tile into registers (hidden under phases 1-2)
        float4 pf[4];
        {
            const float4* src = (const float4*)(g_agg + ((size_t)t*NV + row0)*LL);
            #pragma unroll
            for (int j = 0; j < 4; j++) pf[j] = src[tid + j*512];
        }

        // phase1: Xs(t1) = tanh(hs @ W1 + cz)
        {
            u64 acc[2][4];
            #pragma unroll
            for (int i=0;i<2;i++){ acc[i][0]=0ull; acc[i][1]=0ull; acc[i][2]=0ull; acc[i][3]=0ull; }
            #pragma unroll 4
            for (int k0 = 0; k0 < 64; k0 += 4){
                float4 a0 = *(const float4*)(hs + (p_r0+0)*LL + k0);
                float4 a1 = *(const float4*)(hs + (p_r0+1)*LL + k0);
                #pragma unroll
                for (int kk=0; kk<4; kk++){
                    const u64* wp = (const u64*)(W1s + (k0+kk)*LL + p_c0);
                    u64 w0=wp[0], w1=wp[1], w2=wp[2], w3=wp[3];
                    float v0 = (kk==0)?a0.x:(kk==1)?a0.y:(kk==2)?a0.z:a0.w;
                    float v1 = (kk==0)?a1.x:(kk==1)?a1.y:(kk==2)?a1.z:a1.w;
                    u64 d0 = f2dup(v0), d1 = f2dup(v1);
                    acc[0][0]=f2fma(d0,w0,acc[0][0]); acc[0][1]=f2fma(d0,w1,acc[0][1]);
                    acc[0][2]=f2fma(d0,w2,acc[0][2]); acc[0][3]=f2fma(d0,w3,acc[0][3]);
                    acc[1][0]=f2fma(d1,w0,acc[1][0]); acc[1][1]=f2fma(d1,w1,acc[1][1]);
                    acc[1][2]=f2fma(d1,w2,acc[1][2]); acc[1][3]=f2fma(d1,w3,acc[1][3]);
                }
            }
            #pragma unroll
            for (int i=0;i<2;i++)
                #pragma unroll
                for (int p=0;p<4;p++){
                    float2 v = f2unpk(acc[i][p]);
                    Xs[(p_r0+i)*LL + p_c0 + 2*p    ] = ftanh(v.x + czf[i][2*p  ]);
                    Xs[(p_r0+i)*LL + p_c0 + 2*p + 1] = ftanh(v.y + czf[i][2*p+1]);
                }
        }
        __syncthreads();
        // phase2: hos = hs + Xs @ W2 + b2
        {
            u64 acc[2][4];
            {
                const u64* bp = (const u64*)(b2s + p_c0);
                u64 b0=bp[0], b1=bp[1], b2v=bp[2], b3=bp[3];
                acc[0][0]=b0; acc[0][1]=b1; acc[0][2]=b2v; acc[0][3]=b3;
                acc[1][0]=b0; acc[1][1]=b1; acc[1][2]=b2v; acc[1][3]=b3;
            }
            #pragma unroll 4
            for (int k0 = 0; k0 < 64; k0 += 4){
                float4 a0 = *(const float4*)(Xs + (p_r0+0)*LL + k0);
                float4 a1 = *(const float4*)(Xs + (p_r0+1)*LL + k0);
                #pragma unroll
                for (int kk=0; kk<4; kk++){
                    const u64* wp = (const u64*)(W2s + (k0+kk)*LL + p_c0);
                    u64 w0=wp[0], w1=wp[1], w2=wp[2], w3=wp[3];
                    float v0 = (kk==0)?a0.x:(kk==1)?a0.y:(kk==2)?a0.z:a0.w;
                    float v1 = (kk==0)?a1.x:(kk==1)?a1.y:(kk==2)?a1.z:a1.w;
                    u64 d0 = f2dup(v0), d1 = f2dup(v1);
                    acc[0][0]=f2fma(d0,w0,acc[0][0]); acc[0][1]=f2fma(d0,w1,acc[0][1]);
                    acc[0][2]=f2fma(d0,w2,acc[0][2]); acc[0][3]=f2fma(d0,w3,acc[0][3]);
                    acc[1][0]=f2fma(d1,w0,acc[1][0]); acc[1][1]=f2fma(d1,w1,acc[1][1]);
                    acc[1][2]=f2fma(d1,w2,acc[1][2]); acc[1][3]=f2fma(d1,w3,acc[1][3]);
                }
            }
            #pragma unroll
            for (int i=0;i<2;i++)
                #pragma unroll
                for (int p=0;p<4;p++){
                    float2 v = f2unpk(acc[i][p]);
                    int base = (p_r0+i)*LL + p_c0 + 2*p;
                    hos[base    ] = hs[base    ] + v.x;
                    hos[base + 1] = hs[base + 1] + v.y;
                }
        }
        __syncthreads();
        // store prefetched agg tile into Xs (t1 dead; phase2 readers done)
        #pragma unroll
        for (int j = 0; j < 4; j++) ((float4*)Xs)[tid + j*512] = pf[j];
        __syncthreads();
        // phase3: GRU stacked-K GEMM: A = [hos | agg], n-gate split
        u64 az[4][2], ar[4][2], anh[4][2], ang[4][2];
        {
            const u64* bz = (const u64*)(bs + g_c0);
            const u64* br = (const u64*)(bs + 64 + g_c0);
            const u64* bn = (const u64*)(bs + 128 + g_c0);
            u64 z0=bz[0], z1=bz[1], q0=br[0], q1=br[1], n0=bn[0], n1=bn[1];
            #pragma unroll
            for (int i=0;i<4;i++){ az[i][0]=z0; az[i][1]=z1; ar[i][0]=q0; ar[i][1]=q1;
                                   ang[i][0]=n0; ang[i][1]=n1; anh[i][0]=0ull; anh[i][1]=0ull; }
        }
        #pragma unroll 2
        for (int k0 = 0; k0 < 64; k0 += 4){
            float4 a[4];
            #pragma unroll
            for (int i=0;i<4;i++) a[i] = *(const float4*)(hos + (g_r0+i)*LL + k0);
            #pragma unroll
            for (int kk=0; kk<4; kk++){
                const float* wrow = Wst + (k0+kk)*L3;
                const u64* wz = (const u64*)(wrow + g_c0);
                const u64* wr = (const u64*)(wrow + 64 + g_c0);
                const u64* wn = (const u64*)(wrow + 128 + g_c0);
                u64 wz0=wz[0],wz1=wz[1],wr0=wr[0],wr1=wr[1],wn0=wn[0],wn1=wn[1];
                #pragma unroll
                for (int i=0;i<4;i++){
                    float av = (kk==0)?a[i].x:(kk==1)?a[i].y:(kk==2)?a[i].z:a[i].w;
                    u64 ad = f2dup(av);
                    az [i][0]=f2fma(ad,wz0,az [i][0]); az [i][1]=f2fma(ad,wz1,az [i][1]);
                    ar [i][0]=f2fma(ad,wr0,ar [i][0]); ar [i][1]=f2fma(ad,wr1,ar [i][1]);
                    anh[i][0]=f2fma(ad,wn0,anh[i][0]); anh[i][1]=f2fma(ad,wn1,anh[i][1]);
                }
            }
        }
        #pragma unroll 2
        for (int k0 = 0; k0 < 64; k0 += 4){
            float4 a[4];
            #pragma unroll
            for (int i=0;i<4;i++) a[i] = *(const float4*)(Xs + (g_r0+i)*LL + k0);
            #pragma unroll
            for (int kk=0; kk<4; kk++){
                const float* wrow = Wst + (64 + k0 + kk)*L3;
                const u64* wz = (const u64*)(wrow + g_c0);
                const u64* wr = (const u64*)(wrow + 64 + g_c0);
                const u64* wn = (const u64*)(wrow + 128 + g_c0);
                u64 wz0=wz[0],wz1=wz[1],wr0=wr[0],wr1=wr[1],wn0=wn[0],wn1=wn[1];
                #pragma unroll
                for (int i=0;i<4;i++){
                    float av = (kk==0)?a[i].x:(kk==1)?a[i].y:(kk==2)?a[i].z:a[i].w;
                    u64 ad = f2dup(av);
                    az [i][0]=f2fma(ad,wz0,az [i][0]); az [i][1]=f2fma(ad,wz1,az [i][1]);
                    ar [i][0]=f2fma(ad,wr0,ar [i][0]); ar [i][1]=f2fma(ad,wr1,ar [i][1]);
                    ang[i][0]=f2fma(ad,wn0,ang[i][0]); ang[i][1]=f2fma(ad,wn1,ang[i][1]);
                }
            }
        }
        // NO sync needed: phase3 GEMM reads hos/Xs; gates write hs/g_xe only
        #pragma unroll
        for (int i=0;i<4;i++){
            int r = g_r0 + i;
            float2 vz0=f2unpk(az[i][0]),  vz1=f2unpk(az[i][1]);
            float2 vr0=f2unpk(ar[i][0]),  vr1=f2unpk(ar[i][1]);
            float2 vh0=f2unpk(anh[i][0]), vh1=f2unpk(anh[i][1]);
            float2 vg0=f2unpk(ang[i][0]), vg1=f2unpk(ang[i][1]);
            float zz[4]={vz0.x,vz0.y,vz1.x,vz1.y};
            float rv[4]={vr0.x,vr0.y,vr1.x,vr1.y};
            float nh[4]={vh0.x,vh0.y,vh1.x,vh1.y};
            float ng[4]={vg0.x,vg0.y,vg1.x,vg1.y};
            float hn4[4];
            #pragma unroll
            for (int j=0;j<4;j++){
                float z  = fsigm(zz[j]);
                float rg = fsigm(rv[j]);
                float nn = ftanh(ng[j] + rg*nh[j]);
                float ho = hos[r*LL + g_c0 + j];
                hn4[j] = (1.f-z)*nn + z*ho;
            }
            #pragma unroll
            for (int j=0;j<4;j++) hs[r*LL + g_c0 + j] = hn4[j];
            *(float4*)(g_xe + ((size_t)t*NV + row0 + r)*LL + g_c0)
                = make_float4(hn4[0], hn4[1], hn4[2], hn4[3]);
        }
        __syncthreads();   // hs writes + Xs reads complete before next iteration
    }
}

// ---------------- decoder ----------------
__global__ void k_decode(float* __restrict__ out, const float* __restrict__ W,
                         const float* __restrict__ b){
    __shared__ float zs[32*65];
    __shared__ float Ws[LL*CC];
    __shared__ float bs[CC];
    int blk = blockIdx.x;
    int nv = blk / 5;
    int t0 = (blk % 5) * 32;
    int tid = threadIdx.x;
    for (int i = tid; i < 32*LL; i += 256){
        int tl = i >> 6, l = i & 63, t = t0 + tl;
        zs[tl*65 + l] = (t < TT) ? g_xe[((size_t)t*NV + nv)*LL + l] : 0.f;
    }
    for (int i = tid; i < LL*CC; i += 256) Ws[i] = W[i];
    if (tid < CC) bs[tid] = b[tid];
    __syncthreads();
    for (int o = tid; o < 512; o += 256){
        int c = o >> 5, tl = o & 31, t = t0 + tl;
        if (t >= TT) continue;
        float acc = bs[c];
        #pragma unroll
        for (int l = 0; l < LL; l++) acc += zs[tl*65 + l] * Ws[l*CC + c];
        out[((size_t)nv*CC + c)*TT + t] = acc;
    }
}

// ---------------- launch ----------------
extern "C" void kernel_launch(void* const* d_in, const int* in_sizes, int n_in,
                              void* d_out, int out_size){
    const float* x      = (const float*)d_in[0];
    const int*   ei     = (const int*)  d_in[1];
    const float* attr   = (const float*)d_in[2];
    const float* W_enc  = (const float*)d_in[3];
    const float* b_enc  = (const float*)d_in[4];
    const float* W_gd   = (const float*)d_in[5];
    const float* gd_Wi  = (const float*)d_in[6];
    const float* gd_Wh  = (const float*)d_in[7];
    const float* gd_b   = (const float*)d_in[8];
    const float* W_dom1 = (const float*)d_in[9];
    const float* b_dom1 = (const float*)d_in[10];
    const float* W_dom2 = (const float*)d_in[11];
    const float* b_dom2 = (const float*)d_in[12];
    const float* ode_W1 = (const float*)d_in[13];
    const float* ode_b1 = (const float*)d_in[14];
    const float* ode_W2 = (const float*)d_in[15];
    const float* ode_b2 = (const float*)d_in[16];
    const float* W_gc   = (const float*)d_in[17];
    const float* gc_Wi  = (const float*)d_in[18];
    const float* gc_Wh  = (const float*)d_in[19];
    const float* gc_b   = (const float*)d_in[20];
    const float* W_dec  = (const float*)d_in[21];
    const float* b_dec  = (const float*)d_in[22];
    float* out = (float*)d_out;

    const int SM_DOMS  = (128*L3 + 2*128*LL + L3) * 4;                         // 164608
    const int SM_CORRS = (128*L3 + 4096 + 4096 + 3*128*LL + L3 + 64) * 4;      // 230400
    const int SM_MLP   = (3*4096 + 3*1024 + 3*64) * 4;                         // 62208

    cudaFuncSetAttribute(k_domscan,  cudaFuncAttributeMaxDynamicSharedMemorySize, SM_DOMS);
    cudaFuncSetAttribute(k_corrscan, cudaFuncAttributeMaxDynamicSharedMemorySize, SM_CORRS);
    cudaFuncSetAttribute(k_dommlp,   cudaFuncAttributeMaxDynamicSharedMemorySize, SM_MLP);

    // 1: CSR build + weight folding (one block)
    k_csrfold<<<1, 1024>>>(ei, attr, W_gd, gd_Wi, W_gc, gc_Wi);
    // 2: encoder
    k_encode<<<NV*5, 256>>>(x, W_enc, b_enc);
    // 3: gather ONCE (pass-independent)
    k_agg <<<TT*128, 256>>>();
    // 4: fused persistent domain scan (gi-GEMM + GRU)  <-- ncu capture slot
    k_domscan<<<NV/128, 512, SM_DOMS>>>(gd_Wh, gd_b);
    // 5: domain MLP + cz
    k_dommlp<<<NV/16, 256, SM_MLP>>>(W_dom1, b_dom1, W_dom2, b_dom2, ode_W1, ode_b1);
    // 6: fused persistent correction scan (ODE + gi-GEMM + GRU)
    k_corrscan<<<NV/128, 512, SM_CORRS>>>(ode_W1, ode_W2, ode_b2, gc_Wh, gc_b);
    // 7: decoder
    k_decode<<<NV*5, 256>>>(out, W_dec, b_dec);
}